// round 2
// baseline (speedup 1.0000x reference)
#include <cuda_runtime.h>
#include <math.h>

// ---------------- scratch (no allocation allowed) ----------------
__device__ float g_bufA[33554432];   // 134 MB ping
__device__ float g_bufB[33554432];   // 134 MB pong
__device__ float g_mean[2048];
__device__ float g_rstd[2048];
__device__ float g_psum[8 * 32 * 3];
__device__ float g_pcnt[8 * 32];

// ---------------- 7x7 reflect-pad conv, Cin=3 -> Cout=16, 512x512 ----------------
// block (16,8): out tile 16 wide x 32 high, each thread 4 consecutive rows, all 16 cout.
__global__ __launch_bounds__(128) void k_conv_in(const float* __restrict__ x,
                                                 const float* __restrict__ w,
                                                 const float* __restrict__ bias,
                                                 float* __restrict__ out) {
    __shared__ float ws[2352];           // [co16][ci3][49]
    __shared__ float tile[2508];         // 3 * (38*22)
    const int tx = threadIdx.x, ty = threadIdx.y;
    const int tid = ty * 16 + tx;
    const int ox0 = blockIdx.x * 16, oy0 = blockIdx.y * 32, b = blockIdx.z;

    for (int i = tid; i < 2352; i += 128) ws[i] = w[i];
    for (int i = tid; i < 2508; i += 128) {
        int ci = i / 836, rem = i % 836, r = rem / 22, c = rem % 22;
        int gy = oy0 + r - 3; gy = gy < 0 ? -gy : (gy > 511 ? 1022 - gy : gy);
        int gx = ox0 + c - 3; gx = gx < 0 ? -gx : (gx > 511 ? 1022 - gx : gx);
        tile[i] = x[((size_t)(b * 3 + ci) << 18) + (gy << 9) + gx];
    }
    __syncthreads();

    float a0[16], a1[16], a2[16], a3[16];
#pragma unroll
    for (int co = 0; co < 16; co++) { float bv = bias[co]; a0[co]=bv; a1[co]=bv; a2[co]=bv; a3[co]=bv; }

#pragma unroll 1
    for (int ci = 0; ci < 3; ci++) {
#pragma unroll 1
        for (int ky = 0; ky < 7; ky++) {
            const float* tp = tile + ci * 836 + (4 * ty + ky) * 22 + tx;
            const float* wp = ws + ci * 49 + ky * 7;
#pragma unroll 1
            for (int kx = 0; kx < 7; kx++) {
                float x0 = tp[kx], x1 = tp[kx + 22], x2 = tp[kx + 44], x3 = tp[kx + 66];
                const float* wq = wp + kx;
#pragma unroll
                for (int co = 0; co < 16; co++) {
                    float wv = wq[co * 147];
                    a0[co] += x0 * wv; a1[co] += x1 * wv; a2[co] += x2 * wv; a3[co] += x3 * wv;
                }
            }
        }
    }
    int oy = oy0 + 4 * ty, ox = ox0 + tx;
#pragma unroll
    for (int co = 0; co < 16; co++) {
        float* op = out + ((size_t)(b * 16 + co) << 18) + (oy << 9) + ox;
        op[0] = a0[co]; op[512] = a1[co]; op[1024] = a2[co]; op[1536] = a3[co];
    }
}

// ---------------- 7x7 reflect conv, Cin=16 -> Cout=3, + tanh ----------------
__global__ __launch_bounds__(128) void k_conv_out(const float* __restrict__ in,
                                                  const float* __restrict__ w,
                                                  const float* __restrict__ bias,
                                                  float* __restrict__ out) {
    __shared__ float ws[2352];   // [co3][ci16][49]
    __shared__ float tile[836];  // 38*22 (one ci at a time)
    const int tx = threadIdx.x, ty = threadIdx.y;
    const int tid = ty * 16 + tx;
    const int ox0 = blockIdx.x * 16, oy0 = blockIdx.y * 32, b = blockIdx.z;

    for (int i = tid; i < 2352; i += 128) ws[i] = w[i];

    float a0[3], a1[3], a2[3], a3[3];
#pragma unroll
    for (int co = 0; co < 3; co++) { float bv = bias[co]; a0[co]=bv; a1[co]=bv; a2[co]=bv; a3[co]=bv; }

#pragma unroll 1
    for (int ci = 0; ci < 16; ci++) {
        __syncthreads();
        for (int i = tid; i < 836; i += 128) {
            int r = i / 22, c = i % 22;
            int gy = oy0 + r - 3; gy = gy < 0 ? -gy : (gy > 511 ? 1022 - gy : gy);
            int gx = ox0 + c - 3; gx = gx < 0 ? -gx : (gx > 511 ? 1022 - gx : gx);
            tile[i] = in[((size_t)(b * 16 + ci) << 18) + (gy << 9) + gx];
        }
        __syncthreads();
#pragma unroll 1
        for (int ky = 0; ky < 7; ky++) {
            const float* tp = tile + (4 * ty + ky) * 22 + tx;
            const float* wp = ws + ci * 49 + ky * 7;
#pragma unroll 1
            for (int kx = 0; kx < 7; kx++) {
                float x0 = tp[kx], x1 = tp[kx + 22], x2 = tp[kx + 44], x3 = tp[kx + 66];
#pragma unroll
                for (int co = 0; co < 3; co++) {
                    float wv = wp[co * 784 + kx];
                    a0[co] += x0 * wv; a1[co] += x1 * wv; a2[co] += x2 * wv; a3[co] += x3 * wv;
                }
            }
        }
    }
    int oy = oy0 + 4 * ty, ox = ox0 + tx;
#pragma unroll
    for (int co = 0; co < 3; co++) {
        float* op = out + ((size_t)(b * 3 + co) << 18) + (oy << 9) + ox;
        op[0] = tanhf(a0[co]); op[512] = tanhf(a1[co]);
        op[1024] = tanhf(a2[co]); op[1536] = tanhf(a3[co]);
    }
}

// ---------------- 3x3 stride-2 conv (zero pad 1) ----------------
// block (16,8): out tile 16 wide x 32 high, 4 rows/thread, cout group of 8.
__global__ __launch_bounds__(128) void k_down(const float* __restrict__ in,
                                              const float* __restrict__ w,
                                              const float* __restrict__ bias,
                                              float* __restrict__ out,
                                              int Cin, int Cout, int Hin, int Win) {
    const int Hout = Hin >> 1, Wout = Win >> 1;
    const int groups = Cout >> 3;
    const int b = blockIdx.z / groups, cog = (blockIdx.z % groups) * 8;
    const int ox0 = blockIdx.x * 16, oy0 = blockIdx.y * 32;
    __shared__ float ws[1152];   // [lci16][co8][9]
    __shared__ float tile[2145]; // 65x33
    const int tx = threadIdx.x, ty = threadIdx.y;
    const int tid = ty * 16 + tx;

    float a0[8], a1[8], a2[8], a3[8];
#pragma unroll
    for (int co = 0; co < 8; co++) { float bv = bias[cog + co]; a0[co]=bv; a1[co]=bv; a2[co]=bv; a3[co]=bv; }

    for (int ci0 = 0; ci0 < Cin; ci0 += 16) {
        __syncthreads();
        for (int i = tid; i < 1152; i += 128) {
            int lci = i / 72, rem = i % 72, co = rem / 9, k = rem % 9;
            ws[i] = w[((size_t)(cog + co) * Cin + ci0 + lci) * 9 + k];
        }
        for (int lci = 0; lci < 16; lci++) {
            __syncthreads();
            const float* ip = in + (size_t)(b * Cin + ci0 + lci) * Hin * Win;
            int ybase = 2 * oy0 - 1, xbase = 2 * ox0 - 1;
            for (int i = tid; i < 2145; i += 128) {
                int r = i / 33, c = i % 33;
                int gy = ybase + r, gx = xbase + c;
                tile[i] = ((unsigned)gy < (unsigned)Hin && (unsigned)gx < (unsigned)Win)
                              ? ip[gy * Win + gx] : 0.f;
            }
            __syncthreads();
            const float* wp = ws + lci * 72;
#pragma unroll
            for (int ky = 0; ky < 3; ky++) {
                const float* tp = tile + (8 * ty + ky) * 33 + 2 * tx;
#pragma unroll
                for (int kx = 0; kx < 3; kx++) {
                    float x0 = tp[kx], x1 = tp[kx + 66], x2 = tp[kx + 132], x3 = tp[kx + 198];
#pragma unroll
                    for (int co = 0; co < 8; co++) {
                        float wv = wp[co * 9 + ky * 3 + kx];
                        a0[co] += x0 * wv; a1[co] += x1 * wv; a2[co] += x2 * wv; a3[co] += x3 * wv;
                    }
                }
            }
        }
    }
    int oy = oy0 + 4 * ty, ox = ox0 + tx;
#pragma unroll
    for (int co = 0; co < 8; co++) {
        float* op = out + ((size_t)(b * Cout + cog + co) * Hout + oy) * Wout + ox;
        op[0] = a0[co]; op[Wout] = a1[co]; op[2 * Wout] = a2[co]; op[3 * Wout] = a3[co];
    }
}

// ---------------- transposed 3x3, stride 2, pad 1, output_pad 1 ----------------
// Weight layout (Cin, Cout, 3, 3). block (16,8): out tile 32x32, each thread 2
// vertical 2x2 output quads (8 pixels) x 8 cout -> every weight load feeds 2 FMAs,
// zero warp divergence.
__global__ __launch_bounds__(128) void k_up(const float* __restrict__ in,
                                            const float* __restrict__ w,
                                            const float* __restrict__ bias,
                                            float* __restrict__ out,
                                            int Cin, int Cout, int Hin, int Win) {
    const int Hout = Hin * 2, Wout = Win * 2;
    const int groups = Cout >> 3;
    const int b = blockIdx.z / groups, cog = (blockIdx.z % groups) * 8;
    const int ox0 = blockIdx.x * 32, oy0 = blockIdx.y * 32;
    const int iy0 = oy0 >> 1, ix0 = ox0 >> 1;
    __shared__ float ws[1152];      // [lci16][co8][9]
    __shared__ float tile[4624];    // 16 * 17*17
    const int tx = threadIdx.x, ty = threadIdx.y;
    const int tid = ty * 16 + tx;

    float acc[8][8];
#pragma unroll
    for (int co = 0; co < 8; co++) {
        float bv = bias[cog + co];
#pragma unroll
        for (int p = 0; p < 8; p++) acc[p][co] = bv;
    }

    for (int ci0 = 0; ci0 < Cin; ci0 += 16) {
        __syncthreads();
        for (int i = tid; i < 1152; i += 128) {
            int lci = i / 72, rem = i % 72, co = rem / 9, k = rem % 9;
            ws[i] = w[((size_t)(ci0 + lci) * Cout + cog + co) * 9 + k];
        }
        for (int i = tid; i < 4624; i += 128) {
            int lci = i / 289, rem = i % 289, r = rem / 17, c = rem % 17;
            int iy = iy0 + r, ix = ix0 + c;
            tile[i] = (iy < Hin && ix < Win)
                          ? in[((size_t)(b * Cin + ci0 + lci) * Hin + iy) * Win + ix] : 0.f;
        }
        __syncthreads();
#pragma unroll 1
        for (int lci = 0; lci < 16; lci++) {
            const float* tp = tile + lci * 289 + (2 * ty) * 17 + tx;
            float v00 = tp[0],  v01 = tp[1];
            float v10 = tp[17], v11 = tp[18];
            float v20 = tp[34], v21 = tp[35];
            const float* wp = ws + lci * 72;
#pragma unroll
            for (int co = 0; co < 8; co++) {
                const float* wc = wp + co * 9;
                float w0=wc[0],w1=wc[1],w2=wc[2],w3=wc[3],w4=wc[4],w5=wc[5],w6=wc[6],w7=wc[7],w8=wc[8];
                // quad 0 (rows v0/v1)
                acc[0][co] += v00 * w4;
                acc[1][co] += v01 * w3 + v00 * w5;
                acc[2][co] += v10 * w1 + v00 * w7;
                acc[3][co] += v11 * w0 + v10 * w2 + v01 * w6 + v00 * w8;
                // quad 1 (rows v1/v2)
                acc[4][co] += v10 * w4;
                acc[5][co] += v11 * w3 + v10 * w5;
                acc[6][co] += v20 * w1 + v10 * w7;
                acc[7][co] += v21 * w0 + v20 * w2 + v11 * w6 + v10 * w8;
            }
        }
    }
#pragma unroll
    for (int p = 0; p < 8; p++) {
        int qyi = p >> 2, py = (p >> 1) & 1, px = p & 1;
        int oy = oy0 + 4 * ty + 2 * qyi + py;
        int ox = ox0 + 2 * tx + px;
#pragma unroll
        for (int co = 0; co < 8; co++)
            out[((size_t)(b * Cout + cog + co) * Hout + oy) * Wout + ox] = acc[p][co];
    }
}

// ---------------- instance norm stats (per (b,c)) ----------------
__global__ void k_inorm_stats(const float* __restrict__ x, int HW) {
    int bc = blockIdx.x;
    const float* p = x + (size_t)bc * HW;
    double s1 = 0.0, s2 = 0.0;
    for (int i = threadIdx.x; i < HW; i += 256) {
        float v = p[i];
        s1 += v; s2 += (double)v * v;
    }
    __shared__ double sh1[256], sh2[256];
    sh1[threadIdx.x] = s1; sh2[threadIdx.x] = s2;
    __syncthreads();
    for (int s = 128; s > 0; s >>= 1) {
        if (threadIdx.x < s) { sh1[threadIdx.x] += sh1[threadIdx.x + s]; sh2[threadIdx.x] += sh2[threadIdx.x + s]; }
        __syncthreads();
    }
    if (threadIdx.x == 0) {
        double m = sh1[0] / HW;
        double var = sh2[0] / HW - m * m;
        if (var < 0.0) var = 0.0;
        g_mean[bc] = (float)m;
        g_rstd[bc] = rsqrtf((float)var + 1e-5f);
    }
}

__global__ void k_norm_relu(float* __restrict__ x, int shift, int total) {
    for (int i = blockIdx.x * blockDim.x + threadIdx.x; i < total; i += gridDim.x * blockDim.x) {
        int bc = i >> shift;
        float v = (x[i] - g_mean[bc]) * g_rstd[bc];
        x[i] = v > 0.f ? v : 0.f;
    }
}

// ---------------- per-instance mean pooling ----------------
__global__ void k_pool_zero() {
    int i = threadIdx.x;
    g_pcnt[i] = 0.f;
    g_psum[i] = 0.f; g_psum[i + 256] = 0.f; g_psum[i + 512] = 0.f;
}

__global__ void k_pool_accum(const float* __restrict__ feat, const int* __restrict__ ids) {
    __shared__ float ss[96];
    __shared__ float sc[32];
    int tid = threadIdx.x;
    if (tid < 96) ss[tid] = 0.f;
    if (tid < 32) sc[tid] = 0.f;
    __syncthreads();
    int b = blockIdx.y;
    const int HW = 262144;
    const float* f0 = feat + (size_t)b * 3 * HW;
    const int* idp = ids + (size_t)b * HW;
    for (int i = blockIdx.x * blockDim.x + tid; i < HW; i += gridDim.x * blockDim.x) {
        int id = idp[i];
        atomicAdd(&ss[id * 3 + 0], f0[i]);
        atomicAdd(&ss[id * 3 + 1], f0[i + HW]);
        atomicAdd(&ss[id * 3 + 2], f0[i + 2 * HW]);
        atomicAdd(&sc[id], 1.f);
    }
    __syncthreads();
    if (tid < 96) atomicAdd(&g_psum[b * 96 + tid], ss[tid]);
    if (tid < 32) atomicAdd(&g_pcnt[b * 32 + tid], sc[tid]);
}

__global__ void k_pool_mean() {
    int i = threadIdx.x;  // b*32+id, exactly 256
    float c = g_pcnt[i];
    c = c > 0.f ? c : 1.f;
    g_psum[i * 3 + 0] /= c; g_psum[i * 3 + 1] /= c; g_psum[i * 3 + 2] /= c;
}

__global__ void k_pool_scatter(const int* __restrict__ ids, float* __restrict__ out) {
    const int HW = 262144;
    int total = 8 * HW;
    for (int i = blockIdx.x * blockDim.x + threadIdx.x; i < total; i += gridDim.x * blockDim.x) {
        int b = i >> 18, p = i & (HW - 1);
        int id = ids[i];
        const float* m = &g_psum[(b * 32 + id) * 3];
        out[((size_t)(b * 3 + 0) << 18) + p] = m[0];
        out[((size_t)(b * 3 + 1) << 18) + p] = m[1];
        out[((size_t)(b * 3 + 2) << 18) + p] = m[2];
    }
}

// ---------------- host ----------------
static inline int ilog2i(int v) { int s = 0; while ((1 << s) < v) s++; return s; }

extern "C" void kernel_launch(void* const* d_in, const int* in_sizes, int n_in,
                              void* d_out, int out_size) {
    const float* x     = (const float*)d_in[0];
    const int*   imap  = (const int*)  d_in[1];
    const float* w_in  = (const float*)d_in[2];
    const float* b_in  = (const float*)d_in[3];
    const float* wd[4], *bd[4], *wu[4], *bu[4];
    for (int i = 0; i < 4; i++) {
        wd[i] = (const float*)d_in[4 + 2 * i];
        bd[i] = (const float*)d_in[5 + 2 * i];
        wu[i] = (const float*)d_in[12 + 2 * i];
        bu[i] = (const float*)d_in[13 + 2 * i];
    }
    const float* w_out = (const float*)d_in[20];
    const float* b_out = (const float*)d_in[21];

    float *A, *Bf;
    cudaGetSymbolAddress((void**)&A,  g_bufA);
    cudaGetSymbolAddress((void**)&Bf, g_bufB);
    float* outp = (float*)d_out;

    dim3 blk(16, 8);

    // input conv: x -> A (16ch, 512x512)
    k_conv_in<<<dim3(32, 16, 8), blk>>>(x, w_in, b_in, A);
    k_inorm_stats<<<8 * 16, 256>>>(A, 262144);
    k_norm_relu<<<16384, 256>>>(A, 18, 8 * 16 * 262144);

    int C = 16, H = 512;
    float* src = A; float* dst = Bf;

    // down path
    for (int i = 0; i < 4; i++) {
        int Cout = 2 * C, Hout = H / 2;
        dim3 g(Hout / 16, Hout / 32, 8 * (Cout / 8));
        k_down<<<g, blk>>>(src, wd[i], bd[i], dst, C, Cout, H, H);
        int HW = Hout * Hout;
        int total = 8 * Cout * HW;
        k_inorm_stats<<<8 * Cout, 256>>>(dst, HW);
        int blocks = (total + 255) / 256; if (blocks > 16384) blocks = 16384;
        k_norm_relu<<<blocks, 256>>>(dst, ilog2i(HW), total);
        float* t = src; src = dst; dst = t;
        C = Cout; H = Hout;
    }

    // up path
    for (int i = 0; i < 4; i++) {
        int Cout = C / 2, Hout = 2 * H;
        dim3 g(Hout / 32, Hout / 32, 8 * (Cout / 8));
        k_up<<<g, blk>>>(src, wu[i], bu[i], dst, C, Cout, H, H);
        int HW = Hout * Hout;
        int total = 8 * Cout * HW;
        k_inorm_stats<<<8 * Cout, 256>>>(dst, HW);
        int blocks = (total + 255) / 256; if (blocks > 16384) blocks = 16384;
        k_norm_relu<<<blocks, 256>>>(dst, ilog2i(HW), total);
        float* t = src; src = dst; dst = t;
        C = Cout; H = Hout;
    }

    // output conv + tanh: src(A, 16ch 512x512) -> dst(B, 3ch)
    k_conv_out<<<dim3(32, 16, 8), blk>>>(src, w_out, b_out, dst);

    // instance-mean pooling -> d_out
    k_pool_zero<<<1, 256>>>();
    k_pool_accum<<<dim3(64, 8), 256>>>(dst, imap);
    k_pool_mean<<<1, 256>>>();
    k_pool_scatter<<<8192, 256>>>(imap, outp);
}

// round 6
// speedup vs baseline: 1.1636x; 1.1636x over previous
#include <cuda_runtime.h>
#include <math.h>

// ---------------- scratch arena (no allocation allowed) ----------------
// Layer regions (padded H+2 x W+2 planes except L9):
// L0 conv_in out 16x512, L1..L4 down outs, L5..L8 up outs, L9 conv_out (unpadded)
__device__ float g_act[136600576];
__device__ float g_mean[2048];
__device__ float g_rstd[2048];
__device__ float g_psum[8 * 32 * 3];
__device__ float g_pcnt[8 * 32];

// ---------------- 7x7 reflect conv, 3 -> 16, 512x512, writes padded ----------------
// block(16,8): out tile 16x32, thread = 4 rows x 16 cout
__global__ __launch_bounds__(128) void k_conv_in(const float* __restrict__ x,
                                                 const float* __restrict__ w,
                                                 const float* __restrict__ bias,
                                                 float* __restrict__ out) {
    __shared__ __align__(16) float ws[2352];   // [ci3][k49][co16]
    __shared__ float tile[3 * 38 * 28];        // stride 28 (4*28 % 32 == 16)
    const int tx = threadIdx.x, ty = threadIdx.y;
    const int tid = ty * 16 + tx;
    const int ox0 = blockIdx.x * 16, oy0 = blockIdx.y * 32, b = blockIdx.z;

    for (int i = tid; i < 2352; i += 128) {
        int co = i & 15, rem = i >> 4, ci = rem / 49, k = rem % 49;
        ws[i] = w[co * 147 + ci * 49 + k];
    }
    for (int i = tid; i < 2508; i += 128) {
        int ci = i / 836, rem = i - ci * 836, r = rem / 22, c = rem % 22;
        int gy = oy0 + r - 3; gy = gy < 0 ? -gy : (gy > 511 ? 1022 - gy : gy);
        int gx = ox0 + c - 3; gx = gx < 0 ? -gx : (gx > 511 ? 1022 - gx : gx);
        tile[ci * 1064 + r * 28 + c] = x[((size_t)(b * 3 + ci) << 18) + (gy << 9) + gx];
    }
    __syncthreads();

    float acc[4][16];
#pragma unroll
    for (int co = 0; co < 16; co++) {
        float bv = bias[co];
#pragma unroll
        for (int r = 0; r < 4; r++) acc[r][co] = bv;
    }

#pragma unroll 1
    for (int ci = 0; ci < 3; ci++) {
#pragma unroll 1
        for (int ky = 0; ky < 7; ky++) {
            const float* rp = tile + ci * 1064 + (4 * ty + ky) * 28 + tx;
            const float* wp = ws + (ci * 49 + ky * 7) * 16;
#pragma unroll
            for (int kx = 0; kx < 7; kx++) {
                float x0 = rp[kx], x1 = rp[kx + 28], x2 = rp[kx + 56], x3 = rp[kx + 84];
                float wreg[16];
                *(float4*)(wreg)      = *(const float4*)(wp + kx * 16);
                *(float4*)(wreg + 4)  = *(const float4*)(wp + kx * 16 + 4);
                *(float4*)(wreg + 8)  = *(const float4*)(wp + kx * 16 + 8);
                *(float4*)(wreg + 12) = *(const float4*)(wp + kx * 16 + 12);
#pragma unroll
                for (int co = 0; co < 16; co++) {
                    float wv = wreg[co];
                    acc[0][co] += x0 * wv; acc[1][co] += x1 * wv;
                    acc[2][co] += x2 * wv; acc[3][co] += x3 * wv;
                }
            }
        }
    }
    int oy = oy0 + 4 * ty, ox = ox0 + tx;
#pragma unroll
    for (int co = 0; co < 16; co++) {
        float* op = out + (size_t)(b * 16 + co) * 264196 + (oy + 1) * 514 + ox + 1;
        op[0] = acc[0][co]; op[514] = acc[1][co]; op[1028] = acc[2][co]; op[1542] = acc[3][co];
    }
}

// ---------------- 7x7 reflect conv 16 -> 3 + tanh; reads padded L8, writes unpadded ----------------
// block(16,8): out tile 16x64, thread = 8 rows x 3 cout
__global__ __launch_bounds__(128) void k_conv_out(const float* __restrict__ in,
                                                  const float* __restrict__ w,
                                                  const float* __restrict__ bias,
                                                  float* __restrict__ out) {
    __shared__ __align__(16) float ws[3136];   // [ci16][k49][co4pad]
    __shared__ float tile[4 * 70 * 26];        // 4 ci chunk, stride 26 (8*26 % 32 == 16)
    const int tx = threadIdx.x, ty = threadIdx.y;
    const int tid = ty * 16 + tx;
    const int ox0 = blockIdx.x * 16, oy0 = blockIdx.y * 64, b = blockIdx.z;

    for (int i = tid; i < 3136; i += 128) {
        int co = i & 3, rem = i >> 2, ci = rem / 49, k = rem % 49;
        ws[i] = (co < 3) ? w[co * 784 + ci * 49 + k] : 0.f;
    }

    float acc[8][3];
#pragma unroll
    for (int co = 0; co < 3; co++) {
        float bv = bias[co];
#pragma unroll
        for (int r = 0; r < 8; r++) acc[r][co] = bv;
    }

#pragma unroll 1
    for (int ci0 = 0; ci0 < 16; ci0 += 4) {
        __syncthreads();
        for (int i = tid; i < 6160; i += 128) {
            int lci = i / 1540, rem = i - lci * 1540, r = rem / 22, c = rem % 22;
            int gy = oy0 + r - 3; gy = gy < 0 ? -gy : (gy > 511 ? 1022 - gy : gy);
            int gx = ox0 + c - 3; gx = gx < 0 ? -gx : (gx > 511 ? 1022 - gx : gx);
            tile[lci * 1820 + r * 26 + c] =
                in[(size_t)(b * 16 + ci0 + lci) * 264196 + (gy + 1) * 514 + gx + 1];
        }
        __syncthreads();
#pragma unroll 1
        for (int lci = 0; lci < 4; lci++) {
            int ci = ci0 + lci;
#pragma unroll 1
            for (int ky = 0; ky < 7; ky++) {
                const float* rp = tile + lci * 1820 + (8 * ty + ky) * 26 + tx;
                const float* wp = ws + (ci * 49 + ky * 7) * 4;
#pragma unroll
                for (int kx = 0; kx < 7; kx++) {
                    float4 wv = *(const float4*)(wp + kx * 4);
#pragma unroll
                    for (int r = 0; r < 8; r++) {
                        float xv = rp[kx + r * 26];
                        acc[r][0] += xv * wv.x; acc[r][1] += xv * wv.y; acc[r][2] += xv * wv.z;
                    }
                }
            }
        }
    }
    int ox = ox0 + tx;
#pragma unroll
    for (int r = 0; r < 8; r++) {
        int oy = oy0 + 8 * ty + r;
#pragma unroll
        for (int co = 0; co < 3; co++)
            out[((size_t)(b * 3 + co) << 18) + (oy << 9) + ox] = tanhf(acc[r][co]);
    }
}

// ---------------- 3x3 stride-2 conv; padded in/out ----------------
// block(16,8): out 16x32 tile, thread = 4 rows x 8 cout. E/O split tile, 4ch chunks.
__global__ __launch_bounds__(128) void k_down(const float* __restrict__ in,
                                              const float* __restrict__ w,
                                              const float* __restrict__ bias,
                                              float* __restrict__ out,
                                              int Cin, int Cout, int Hin) {
    const int Wp = Hin + 2, PPin = Wp * Wp;
    const int Hout = Hin >> 1, Wop = Hout + 2, PPout = Wop * Wop;
    const int groups = Cout >> 3;
    const int b = blockIdx.z / groups, cog = (blockIdx.z % groups) * 8;
    const int ox0 = blockIdx.x * 16, oy0 = blockIdx.y * 32;
    __shared__ float tile[4 * 65 * 34];            // E cols 0..16, O cols 17..33; stride 34
    __shared__ __align__(16) float ws[4 * 9 * 8];  // [lci][k][co]
    const int tx = threadIdx.x, ty = threadIdx.y;
    const int tid = ty * 16 + tx;
    const int ybase = 2 * oy0, xbase = 2 * ox0;    // padded coords

    float acc[4][8];
#pragma unroll
    for (int co = 0; co < 8; co++) {
        float bv = bias[cog + co];
#pragma unroll
        for (int r = 0; r < 4; r++) acc[r][co] = bv;
    }

    for (int ci0 = 0; ci0 < Cin; ci0 += 4) {
        __syncthreads();
        for (int i = tid; i < 288; i += 128) {
            int co = i & 7, rem = i >> 3, lci = rem / 9, k = rem % 9;
            ws[i] = w[((size_t)(cog + co) * Cin + ci0 + lci) * 9 + k];
        }
        const float* ip = in + (size_t)(b * Cin + ci0) * PPin;
        for (int i = tid; i < 8840; i += 128) {
            int lci = i / 2210, rem = i - lci * 2210, r = rem / 34, c = rem - r * 34;
            float v = ip[lci * PPin + (ybase + r) * Wp + xbase + c];
            tile[lci * 2210 + r * 34 + (c & 1) * 17 + (c >> 1)] = v;
        }
        __syncthreads();
#pragma unroll 1
        for (int lci = 0; lci < 4; lci++) {
            const float* tl = tile + lci * 2210 + (8 * ty) * 34;
            const float* wl = ws + lci * 72;
#pragma unroll
            for (int ky = 0; ky < 3; ky++) {
#pragma unroll
                for (int kx = 0; kx < 3; kx++) {
                    int off = ky * 34 + (kx & 1) * 17 + tx + (kx >> 1);
                    float x0 = tl[off], x1 = tl[off + 68], x2 = tl[off + 136], x3 = tl[off + 204];
                    float wreg[8];
                    *(float4*)(wreg)     = *(const float4*)(wl + (ky * 3 + kx) * 8);
                    *(float4*)(wreg + 4) = *(const float4*)(wl + (ky * 3 + kx) * 8 + 4);
#pragma unroll
                    for (int co = 0; co < 8; co++) {
                        float wv = wreg[co];
                        acc[0][co] += x0 * wv; acc[1][co] += x1 * wv;
                        acc[2][co] += x2 * wv; acc[3][co] += x3 * wv;
                    }
                }
            }
        }
    }
    int oy = oy0 + 4 * ty, ox = ox0 + tx;
#pragma unroll
    for (int co = 0; co < 8; co++) {
        float* op = out + (size_t)(b * Cout + cog + co) * PPout + (oy + 1) * Wop + ox + 1;
        op[0] = acc[0][co]; op[Wop] = acc[1][co];
        op[2 * Wop] = acc[2][co]; op[3 * Wop] = acc[3][co];
    }
}

// ---------------- transposed 3x3 s2 p1 op1; padded in/out ----------------
// block(16,8): out 32x32 tile, thread = 2 vertical 2x2 quads x 8 cout
// Weight flat k: w0..w8 = w[ky][kx] row-major; wa={w0..w3}, wb={w4..w7}.
__global__ __launch_bounds__(128) void k_up(const float* __restrict__ in,
                                            const float* __restrict__ w,
                                            const float* __restrict__ bias,
                                            float* __restrict__ out,
                                            int Cin, int Cout, int Hin) {
    const int Wp = Hin + 2, PPin = Wp * Wp;
    const int Hout = Hin * 2, Wop = Hout + 2, PPout = Wop * Wop;
    const int groups = Cout >> 3;
    const int b = blockIdx.z / groups, cog = (blockIdx.z % groups) * 8;
    const int ox0 = blockIdx.x * 32, oy0 = blockIdx.y * 32;
    const int iy0 = oy0 >> 1, ix0 = ox0 >> 1;
    __shared__ float tile[4 * 17 * 24];            // stride 24 (2*24 % 32 == 16)
    __shared__ __align__(16) float ws[4 * 8 * 12]; // [lci][co][12pad]
    const int tx = threadIdx.x, ty = threadIdx.y;
    const int tid = ty * 16 + tx;

    float acc[8][8];
#pragma unroll
    for (int co = 0; co < 8; co++) {
        float bv = bias[cog + co];
#pragma unroll
        for (int p = 0; p < 8; p++) acc[p][co] = bv;
    }

    for (int ci0 = 0; ci0 < Cin; ci0 += 4) {
        __syncthreads();
        for (int i = tid; i < 288; i += 128) {
            int lci = i / 72, rem = i - lci * 72, co = rem / 9, k = rem % 9;
            ws[lci * 96 + co * 12 + k] = w[((size_t)(ci0 + lci) * Cout + cog + co) * 9 + k];
        }
        const float* ip = in + (size_t)(b * Cin + ci0) * PPin;
        for (int i = tid; i < 1156; i += 128) {
            int lci = i / 289, rem = i - lci * 289, r = rem / 17, c = rem - r * 17;
            tile[lci * 408 + r * 24 + c] = ip[lci * PPin + (iy0 + r + 1) * Wp + ix0 + c + 1];
        }
        __syncthreads();
#pragma unroll 1
        for (int lci = 0; lci < 4; lci++) {
            const float* tp = tile + lci * 408 + (2 * ty) * 24 + tx;
            float v00 = tp[0],  v01 = tp[1];
            float v10 = tp[24], v11 = tp[25];
            float v20 = tp[48], v21 = tp[49];
            const float* wl = ws + lci * 96;
#pragma unroll
            for (int co = 0; co < 8; co++) {
                float4 wa = *(const float4*)(wl + co * 12);   // w0 w1 w2 w3
                float4 wb = *(const float4*)(wl + co * 12 + 4); // w4 w5 w6 w7
                float w8 = wl[co * 12 + 8];
                // out(2r,2c)     = v00*w4
                acc[0][co] += v00 * wb.x;
                // out(2r,2c+1)   = v01*w3 + v00*w5
                acc[1][co] += v01 * wa.w + v00 * wb.y;
                // out(2r+1,2c)   = v10*w1 + v00*w7
                acc[2][co] += v10 * wa.y + v00 * wb.w;
                // out(2r+1,2c+1) = v11*w0 + v10*w2 + v01*w6 + v00*w8
                acc[3][co] += v11 * wa.x + v10 * wa.z + v01 * wb.z + v00 * w8;
                // quad 1 (rows shifted by one input row)
                acc[4][co] += v10 * wb.x;
                acc[5][co] += v11 * wa.w + v10 * wb.y;
                acc[6][co] += v20 * wa.y + v10 * wb.w;
                acc[7][co] += v21 * wa.x + v20 * wa.z + v11 * wb.z + v10 * w8;
            }
        }
    }
#pragma unroll
    for (int p = 0; p < 8; p++) {
        int qyi = p >> 2, py = (p >> 1) & 1, px = p & 1;
        int oy = oy0 + 4 * ty + 2 * qyi + py;
        int ox = ox0 + 2 * tx + px;
#pragma unroll
        for (int co = 0; co < 8; co++)
            out[(size_t)(b * Cout + cog + co) * PPout + (oy + 1) * Wop + ox + 1] = acc[p][co];
    }
}

// ---------------- instance norm stats (per (b,c)) on padded planes ----------------
__global__ void k_stats(const float* __restrict__ base, int W, int logW) {
    int bc = blockIdx.x;
    const float* p = base + (size_t)bc * (W + 2) * (W + 2);
    int HW = W << logW;
    double s1 = 0.0, s2 = 0.0;
    for (int i = threadIdx.x; i < HW; i += 256) {
        int r = i >> logW, c = i & (W - 1);
        float v = p[(r + 1) * (W + 2) + c + 1];
        s1 += v; s2 += (double)v * v;
    }
    __shared__ double sh1[256], sh2[256];
    sh1[threadIdx.x] = s1; sh2[threadIdx.x] = s2;
    __syncthreads();
    for (int s = 128; s > 0; s >>= 1) {
        if (threadIdx.x < s) { sh1[threadIdx.x] += sh1[threadIdx.x + s]; sh2[threadIdx.x] += sh2[threadIdx.x + s]; }
        __syncthreads();
    }
    if (threadIdx.x == 0) {
        double m = sh1[0] / HW;
        double var = sh2[0] / HW - m * m;
        if (var < 0.0) var = 0.0;
        g_mean[bc] = (float)m;
        g_rstd[bc] = rsqrtf((float)var + 1e-5f);
    }
}

__global__ void k_norm_relu(float* __restrict__ base, int logW, int total) {
    int W = 1 << logW;
    for (int i = blockIdx.x * blockDim.x + threadIdx.x; i < total; i += gridDim.x * blockDim.x) {
        int bc = i >> (2 * logW);
        int r = (i >> logW) & (W - 1), c = i & (W - 1);
        size_t addr = (size_t)bc * (W + 2) * (W + 2) + (r + 1) * (W + 2) + c + 1;
        float v = (base[addr] - g_mean[bc]) * g_rstd[bc];
        base[addr] = v > 0.f ? v : 0.f;
    }
}

// ---------------- per-instance mean pooling ----------------
__global__ void k_pool_zero() {
    int i = threadIdx.x;
    g_pcnt[i] = 0.f;
    g_psum[i] = 0.f; g_psum[i + 256] = 0.f; g_psum[i + 512] = 0.f;
}

__global__ void k_pool_accum(const float* __restrict__ feat, const int* __restrict__ ids) {
    __shared__ float ss[96];
    __shared__ float sc[32];
    int tid = threadIdx.x;
    if (tid < 96) ss[tid] = 0.f;
    if (tid < 32) sc[tid] = 0.f;
    __syncthreads();
    int b = blockIdx.y;
    const int HW = 262144;
    const float* f0 = feat + (size_t)b * 3 * HW;
    const int* idp = ids + (size_t)b * HW;
    for (int i = blockIdx.x * blockDim.x + tid; i < HW; i += gridDim.x * blockDim.x) {
        int id = idp[i];
        atomicAdd(&ss[id * 3 + 0], f0[i]);
        atomicAdd(&ss[id * 3 + 1], f0[i + HW]);
        atomicAdd(&ss[id * 3 + 2], f0[i + 2 * HW]);
        atomicAdd(&sc[id], 1.f);
    }
    __syncthreads();
    if (tid < 96) atomicAdd(&g_psum[b * 96 + tid], ss[tid]);
    if (tid < 32) atomicAdd(&g_pcnt[b * 32 + tid], sc[tid]);
}

__global__ void k_pool_mean() {
    int i = threadIdx.x;
    float c = g_pcnt[i];
    c = c > 0.f ? c : 1.f;
    g_psum[i * 3 + 0] /= c; g_psum[i * 3 + 1] /= c; g_psum[i * 3 + 2] /= c;
}

__global__ void k_pool_scatter(const int* __restrict__ ids, float* __restrict__ out) {
    const int HW = 262144;
    int total = 8 * HW;
    for (int i = blockIdx.x * blockDim.x + threadIdx.x; i < total; i += gridDim.x * blockDim.x) {
        int b = i >> 18, p = i & (HW - 1);
        int id = ids[i];
        const float* m = &g_psum[(b * 32 + id) * 3];
        out[((size_t)(b * 3 + 0) << 18) + p] = m[0];
        out[((size_t)(b * 3 + 1) << 18) + p] = m[1];
        out[((size_t)(b * 3 + 2) << 18) + p] = m[2];
    }
}

// ---------------- host ----------------
static inline int ilog2i(int v) { int s = 0; while ((1 << s) < v) s++; return s; }

extern "C" void kernel_launch(void* const* d_in, const int* in_sizes, int n_in,
                              void* d_out, int out_size) {
    const float* x     = (const float*)d_in[0];
    const int*   imap  = (const int*)  d_in[1];
    const float* w_in  = (const float*)d_in[2];
    const float* b_in  = (const float*)d_in[3];
    const float* wd[4], *bd[4], *wu[4], *bu[4];
    for (int i = 0; i < 4; i++) {
        wd[i] = (const float*)d_in[4 + 2 * i];
        bd[i] = (const float*)d_in[5 + 2 * i];
        wu[i] = (const float*)d_in[12 + 2 * i];
        bu[i] = (const float*)d_in[13 + 2 * i];
    }
    const float* w_out = (const float*)d_in[20];
    const float* b_out = (const float*)d_in[21];

    static const size_t OFF[10] = {
        0u, 33817088u, 50857472u, 59510272u, 63970816u, 66338304u,
        70798848u, 79451648u, 96492032u, 130309120u
    };

    float* act;
    cudaGetSymbolAddress((void**)&act, g_act);
    float* outp = (float*)d_out;

    // zero all padded layers (halos must be 0; interiors get overwritten)
    cudaMemsetAsync(act, 0, OFF[9] * sizeof(float));

    dim3 blk(16, 8);

    // input conv -> L0 (16ch, padded 514)
    k_conv_in<<<dim3(32, 16, 8), blk>>>(x, w_in, b_in, act + OFF[0]);
    k_stats<<<8 * 16, 256>>>(act + OFF[0], 512, 9);
    k_norm_relu<<<16384, 256>>>(act + OFF[0], 9, 8 * 16 * 262144);

    int C = 16, H = 512;
    // down path: L_i -> L_{i+1}
    for (int i = 0; i < 4; i++) {
        int Cout = 2 * C, Hout = H / 2;
        dim3 g(Hout / 16, Hout / 32, 8 * (Cout / 8));
        k_down<<<g, blk>>>(act + OFF[i], wd[i], bd[i], act + OFF[i + 1], C, Cout, H);
        int logW = ilog2i(Hout);
        int total = 8 * Cout * Hout * Hout;
        k_stats<<<8 * Cout, 256>>>(act + OFF[i + 1], Hout, logW);
        int blocks = (total + 255) / 256; if (blocks > 16384) blocks = 16384;
        k_norm_relu<<<blocks, 256>>>(act + OFF[i + 1], logW, total);
        C = Cout; H = Hout;
    }

    // up path: L_{4+i} -> L_{5+i}
    for (int i = 0; i < 4; i++) {
        int Cout = C / 2, Hout = 2 * H;
        dim3 g(Hout / 32, Hout / 32, 8 * (Cout / 8));
        k_up<<<g, blk>>>(act + OFF[4 + i], wu[i], bu[i], act + OFF[5 + i], C, Cout, H);
        int logW = ilog2i(Hout);
        int total = 8 * Cout * Hout * Hout;
        k_stats<<<8 * Cout, 256>>>(act + OFF[5 + i], Hout, logW);
        int blocks = (total + 255) / 256; if (blocks > 16384) blocks = 16384;
        k_norm_relu<<<blocks, 256>>>(act + OFF[5 + i], logW, total);
        C = Cout; H = Hout;
    }

    // output conv + tanh: L8 -> L9 (unpadded)
    k_conv_out<<<dim3(32, 8, 8), blk>>>(act + OFF[8], w_out, b_out, act + OFF[9]);

    // instance-mean pooling -> d_out
    k_pool_zero<<<1, 256>>>();
    k_pool_accum<<<dim3(64, 8), 256>>>(act + OFF[9], imap);
    k_pool_mean<<<1, 256>>>();
    k_pool_scatter<<<8192, 256>>>(imap, outp);
}

// round 10
// speedup vs baseline: 1.2195x; 1.0480x over previous
#include <cuda_runtime.h>
#include <math.h>

// ---------------- scratch arena (no allocation allowed) ----------------
// Padded H+2 x W+2 planes, L9 (conv_out) unpadded.
__device__ float g_act[136600576];
__device__ float g_mean[2048];
__device__ float g_rstd[2048];
__device__ float g_psum[8 * 32 * 3];
__device__ float g_pcnt[8 * 32];

// ---------------- 7x7 reflect conv, 3 -> 16, 512x512, writes padded (raw) ----------------
__global__ __launch_bounds__(128) void k_conv_in(const float* __restrict__ x,
                                                 const float* __restrict__ w,
                                                 const float* __restrict__ bias,
                                                 float* __restrict__ out) {
    __shared__ __align__(16) float ws[2352];   // [ci3][k49][co16]
    __shared__ float tile[3 * 38 * 28];
    const int tx = threadIdx.x, ty = threadIdx.y;
    const int tid = ty * 16 + tx;
    const int ox0 = blockIdx.x * 16, oy0 = blockIdx.y * 32, b = blockIdx.z;

    for (int i = tid; i < 2352; i += 128) {
        int co = i & 15, rem = i >> 4, ci = rem / 49, k = rem % 49;
        ws[i] = w[co * 147 + ci * 49 + k];
    }
    for (int i = tid; i < 2508; i += 128) {
        int ci = i / 836, rem = i - ci * 836, r = rem / 22, c = rem % 22;
        int gy = oy0 + r - 3; gy = gy < 0 ? -gy : (gy > 511 ? 1022 - gy : gy);
        int gx = ox0 + c - 3; gx = gx < 0 ? -gx : (gx > 511 ? 1022 - gx : gx);
        tile[ci * 1064 + r * 28 + c] = x[((size_t)(b * 3 + ci) << 18) + (gy << 9) + gx];
    }
    __syncthreads();

    float acc[4][16];
#pragma unroll
    for (int co = 0; co < 16; co++) {
        float bv = bias[co];
#pragma unroll
        for (int r = 0; r < 4; r++) acc[r][co] = bv;
    }

#pragma unroll 1
    for (int ci = 0; ci < 3; ci++) {
#pragma unroll 1
        for (int ky = 0; ky < 7; ky++) {
            const float* rp = tile + ci * 1064 + (4 * ty + ky) * 28 + tx;
            const float* wp = ws + (ci * 49 + ky * 7) * 16;
#pragma unroll
            for (int kx = 0; kx < 7; kx++) {
                float x0 = rp[kx], x1 = rp[kx + 28], x2 = rp[kx + 56], x3 = rp[kx + 84];
                float wreg[16];
                *(float4*)(wreg)      = *(const float4*)(wp + kx * 16);
                *(float4*)(wreg + 4)  = *(const float4*)(wp + kx * 16 + 4);
                *(float4*)(wreg + 8)  = *(const float4*)(wp + kx * 16 + 8);
                *(float4*)(wreg + 12) = *(const float4*)(wp + kx * 16 + 12);
#pragma unroll
                for (int co = 0; co < 16; co++) {
                    float wv = wreg[co];
                    acc[0][co] += x0 * wv; acc[1][co] += x1 * wv;
                    acc[2][co] += x2 * wv; acc[3][co] += x3 * wv;
                }
            }
        }
    }
    int oy = oy0 + 4 * ty, ox = ox0 + tx;
#pragma unroll
    for (int co = 0; co < 16; co++) {
        float* op = out + (size_t)(b * 16 + co) * 264196 + (oy + 1) * 514 + ox + 1;
        op[0] = acc[0][co]; op[514] = acc[1][co]; op[1028] = acc[2][co]; op[1542] = acc[3][co];
    }
}

// ---------------- 7x7 reflect conv 16 -> 3 + tanh; norm+relu fused on load ----------------
__global__ __launch_bounds__(128) void k_conv_out(const float* __restrict__ in,
                                                  const float* __restrict__ w,
                                                  const float* __restrict__ bias,
                                                  float* __restrict__ out) {
    __shared__ __align__(16) float ws[3136];   // [ci16][k49][co4pad]
    __shared__ float tile[4 * 70 * 26];
    const int tx = threadIdx.x, ty = threadIdx.y;
    const int tid = ty * 16 + tx;
    const int ox0 = blockIdx.x * 16, oy0 = blockIdx.y * 64, b = blockIdx.z;

    for (int i = tid; i < 3136; i += 128) {
        int co = i & 3, rem = i >> 2, ci = rem / 49, k = rem % 49;
        ws[i] = (co < 3) ? w[co * 784 + ci * 49 + k] : 0.f;
    }

    float acc[8][3];
#pragma unroll
    for (int co = 0; co < 3; co++) {
        float bv = bias[co];
#pragma unroll
        for (int r = 0; r < 8; r++) acc[r][co] = bv;
    }

#pragma unroll 1
    for (int ci0 = 0; ci0 < 16; ci0 += 4) {
        __syncthreads();
        for (int i = tid; i < 6160; i += 128) {
            int lci = i / 1540, rem = i - lci * 1540, r = rem / 22, c = rem % 22;
            int gy = oy0 + r - 3; gy = gy < 0 ? -gy : (gy > 511 ? 1022 - gy : gy);
            int gx = ox0 + c - 3; gx = gx < 0 ? -gx : (gx > 511 ? 1022 - gx : gx);
            int bc = b * 16 + ci0 + lci;
            float v = in[(size_t)bc * 264196 + (gy + 1) * 514 + gx + 1];
            tile[lci * 1820 + r * 26 + c] = fmaxf(0.f, (v - g_mean[bc]) * g_rstd[bc]);
        }
        __syncthreads();
#pragma unroll 1
        for (int lci = 0; lci < 4; lci++) {
            int ci = ci0 + lci;
#pragma unroll 1
            for (int ky = 0; ky < 7; ky++) {
                const float* rp = tile + lci * 1820 + (8 * ty + ky) * 26 + tx;
                const float* wp = ws + (ci * 49 + ky * 7) * 4;
#pragma unroll
                for (int kx = 0; kx < 7; kx++) {
                    float4 wv = *(const float4*)(wp + kx * 4);
#pragma unroll
                    for (int r = 0; r < 8; r++) {
                        float xv = rp[kx + r * 26];
                        acc[r][0] += xv * wv.x; acc[r][1] += xv * wv.y; acc[r][2] += xv * wv.z;
                    }
                }
            }
        }
    }
    int ox = ox0 + tx;
#pragma unroll
    for (int r = 0; r < 8; r++) {
        int oy = oy0 + 8 * ty + r;
#pragma unroll
        for (int co = 0; co < 3; co++)
            out[((size_t)(b * 3 + co) << 18) + (oy << 9) + ox] = tanhf(acc[r][co]);
    }
}

// ---------------- 3x3 stride-2 conv; norm+relu fused on load; div-free float2 loads ----------------
// block(16,8): out 16x32 tile, thread = 4 rows x 8 cout. E/O split smem tile.
__global__ __launch_bounds__(128) void k_down(const float* __restrict__ in,
                                              const float* __restrict__ w,
                                              const float* __restrict__ bias,
                                              float* __restrict__ out,
                                              int Cin, int Cout, int Hin) {
    const int Wp = Hin + 2, PPin = Wp * Wp;
    const int Hout = Hin >> 1, Wop = Hout + 2, PPout = Wop * Wop;
    const int groups = Cout >> 3;
    const int b = blockIdx.z / groups, cog = (blockIdx.z % groups) * 8;
    const int ox0 = blockIdx.x * 16, oy0 = blockIdx.y * 32;
    __shared__ float tile[4 * 65 * 34];            // E cols 0..16, O cols 17..33; stride 34
    __shared__ __align__(16) float ws[4 * 9 * 8];  // [lci][k][co]
    const int tx = threadIdx.x, ty = threadIdx.y;
    const int tid = ty * 16 + tx;
    const int ybase = 2 * oy0, xbase = 2 * ox0;    // padded coords

    float acc[4][8];
#pragma unroll
    for (int co = 0; co < 8; co++) {
        float bv = bias[cog + co];
#pragma unroll
        for (int r = 0; r < 4; r++) acc[r][co] = bv;
    }

    for (int ci0 = 0; ci0 < Cin; ci0 += 4) {
        __syncthreads();
        for (int i = tid; i < 288; i += 128) {
            int co = i & 7, rem = i >> 3, lci = rem / 9, k = rem % 9;
            ws[i] = w[((size_t)(cog + co) * Cin + ci0 + lci) * 9 + k];
        }
        const int bcb = b * Cin + ci0;
#pragma unroll 1
        for (int lci = 0; lci < 4; lci++) {
            float m = g_mean[bcb + lci], rs = g_rstd[bcb + lci];
            const float* ip = in + (size_t)(bcb + lci) * PPin + (size_t)ybase * Wp + xbase;
            float* tp = tile + lci * 2210;
#pragma unroll 1
            for (int r = ty; r < 65; r += 8) {
                float2 v = *(const float2*)(ip + r * Wp + 2 * tx);
                tp[r * 34 + tx]      = fmaxf(0.f, (v.x - m) * rs);
                tp[r * 34 + 17 + tx] = fmaxf(0.f, (v.y - m) * rs);
            }
            if (tid < 65) {   // float2 col 16 = input cols 32,33
                float2 v = *(const float2*)(ip + tid * Wp + 32);
                tp[tid * 34 + 16] = fmaxf(0.f, (v.x - m) * rs);
                tp[tid * 34 + 33] = fmaxf(0.f, (v.y - m) * rs);
            }
        }
        __syncthreads();
#pragma unroll 1
        for (int lci = 0; lci < 4; lci++) {
            const float* tl = tile + lci * 2210 + (8 * ty) * 34;
            const float* wl = ws + lci * 72;
#pragma unroll
            for (int ky = 0; ky < 3; ky++) {
#pragma unroll
                for (int kx = 0; kx < 3; kx++) {
                    int off = ky * 34 + (kx & 1) * 17 + tx + (kx >> 1);
                    float x0 = tl[off], x1 = tl[off + 68], x2 = tl[off + 136], x3 = tl[off + 204];
                    float wreg[8];
                    *(float4*)(wreg)     = *(const float4*)(wl + (ky * 3 + kx) * 8);
                    *(float4*)(wreg + 4) = *(const float4*)(wl + (ky * 3 + kx) * 8 + 4);
#pragma unroll
                    for (int co = 0; co < 8; co++) {
                        float wv = wreg[co];
                        acc[0][co] += x0 * wv; acc[1][co] += x1 * wv;
                        acc[2][co] += x2 * wv; acc[3][co] += x3 * wv;
                    }
                }
            }
        }
    }
    int oy = oy0 + 4 * ty, ox = ox0 + tx;
#pragma unroll
    for (int co = 0; co < 8; co++) {
        float* op = out + (size_t)(b * Cout + cog + co) * PPout + (oy + 1) * Wop + ox + 1;
        op[0] = acc[0][co]; op[Wop] = acc[1][co];
        op[2 * Wop] = acc[2][co]; op[3 * Wop] = acc[3][co];
    }
}

// ---------------- transposed 3x3 s2 p1 op1; norm+relu fused on load; div-free loads ----------------
__global__ __launch_bounds__(128) void k_up(const float* __restrict__ in,
                                            const float* __restrict__ w,
                                            const float* __restrict__ bias,
                                            float* __restrict__ out,
                                            int Cin, int Cout, int Hin) {
    const int Wp = Hin + 2, PPin = Wp * Wp;
    const int Hout = Hin * 2, Wop = Hout + 2, PPout = Wop * Wop;
    const int groups = Cout >> 3;
    const int b = blockIdx.z / groups, cog = (blockIdx.z % groups) * 8;
    const int ox0 = blockIdx.x * 32, oy0 = blockIdx.y * 32;
    const int iy0 = oy0 >> 1, ix0 = ox0 >> 1;
    __shared__ float tile[4 * 17 * 24];
    __shared__ __align__(16) float ws[4 * 8 * 12]; // [lci][co][12pad]
    const int tx = threadIdx.x, ty = threadIdx.y;
    const int tid = ty * 16 + tx;

    float acc[8][8];
#pragma unroll
    for (int co = 0; co < 8; co++) {
        float bv = bias[cog + co];
#pragma unroll
        for (int p = 0; p < 8; p++) acc[p][co] = bv;
    }

    for (int ci0 = 0; ci0 < Cin; ci0 += 4) {
        __syncthreads();
        for (int i = tid; i < 288; i += 128) {
            int lci = i / 72, rem = i - lci * 72, co = rem / 9, k = rem % 9;
            ws[lci * 96 + co * 12 + k] = w[((size_t)(ci0 + lci) * Cout + cog + co) * 9 + k];
        }
        const int bcb = b * Cin + ci0;
#pragma unroll 1
        for (int lci = 0; lci < 4; lci++) {
            float m = g_mean[bcb + lci], rs = g_rstd[bcb + lci];
            const float* ip = in + (size_t)(bcb + lci) * PPin + (size_t)(iy0 + 1) * Wp + ix0 + 1;
            float* tp = tile + lci * 408;
#pragma unroll 1
            for (int r = ty; r < 17; r += 8) {
                float v = ip[r * Wp + tx];
                tp[r * 24 + tx] = fmaxf(0.f, (v - m) * rs);
                if (tx == 0) {
                    float v2 = ip[r * Wp + 16];
                    tp[r * 24 + 16] = fmaxf(0.f, (v2 - m) * rs);
                }
            }
        }
        __syncthreads();
#pragma unroll 1
        for (int lci = 0; lci < 4; lci++) {
            const float* tp = tile + lci * 408 + (2 * ty) * 24 + tx;
            float v00 = tp[0],  v01 = tp[1];
            float v10 = tp[24], v11 = tp[25];
            float v20 = tp[48], v21 = tp[49];
            const float* wl = ws + lci * 96;
#pragma unroll
            for (int co = 0; co < 8; co++) {
                float4 wa = *(const float4*)(wl + co * 12);     // w0 w1 w2 w3
                float4 wb = *(const float4*)(wl + co * 12 + 4); // w4 w5 w6 w7
                float w8 = wl[co * 12 + 8];
                acc[0][co] += v00 * wb.x;
                acc[1][co] += v01 * wa.w + v00 * wb.y;
                acc[2][co] += v10 * wa.y + v00 * wb.w;
                acc[3][co] += v11 * wa.x + v10 * wa.z + v01 * wb.z + v00 * w8;
                acc[4][co] += v10 * wb.x;
                acc[5][co] += v11 * wa.w + v10 * wb.y;
                acc[6][co] += v20 * wa.y + v10 * wb.w;
                acc[7][co] += v21 * wa.x + v20 * wa.z + v11 * wb.z + v10 * w8;
            }
        }
    }
#pragma unroll
    for (int p = 0; p < 8; p++) {
        int qyi = p >> 2, py = (p >> 1) & 1, px = p & 1;
        int oy = oy0 + 4 * ty + 2 * qyi + py;
        int ox = ox0 + 2 * tx + px;
#pragma unroll
        for (int co = 0; co < 8; co++)
            out[(size_t)(b * Cout + cog + co) * PPout + (oy + 1) * Wop + ox + 1] = acc[p][co];
    }
}

// ---------------- instance norm stats (per (b,c)) on padded planes ----------------
__global__ void k_stats(const float* __restrict__ base, int W, int logW) {
    int bc = blockIdx.x;
    const float* p = base + (size_t)bc * (W + 2) * (W + 2);
    int HW = W << logW;
    double s1 = 0.0, s2 = 0.0;
    for (int i = threadIdx.x; i < HW; i += 256) {
        int r = i >> logW, c = i & (W - 1);
        float v = p[(r + 1) * (W + 2) + c + 1];
        s1 += v; s2 += (double)v * v;
    }
    __shared__ double sh1[256], sh2[256];
    sh1[threadIdx.x] = s1; sh2[threadIdx.x] = s2;
    __syncthreads();
    for (int s = 128; s > 0; s >>= 1) {
        if (threadIdx.x < s) { sh1[threadIdx.x] += sh1[threadIdx.x + s]; sh2[threadIdx.x] += sh2[threadIdx.x + s]; }
        __syncthreads();
    }
    if (threadIdx.x == 0) {
        double m = sh1[0] / HW;
        double var = sh2[0] / HW - m * m;
        if (var < 0.0) var = 0.0;
        g_mean[bc] = (float)m;
        g_rstd[bc] = rsqrtf((float)var + 1e-5f);
    }
}

// Fill halo of each plane with mean[bc]: normalizes to exactly 0 (then relu->0).
__global__ void k_halo(float* __restrict__ base, int W) {
    int bc = blockIdx.x;
    float m = g_mean[bc];
    int Wp = W + 2;
    float* p = base + (size_t)bc * Wp * Wp;
    for (int i = threadIdx.x; i < Wp; i += 256) {
        p[i] = m;
        p[(size_t)(Wp - 1) * Wp + i] = m;
        p[(size_t)i * Wp] = m;
        p[(size_t)i * Wp + Wp - 1] = m;
    }
}

// ---------------- per-instance mean pooling ----------------
__global__ void k_pool_zero() {
    int i = threadIdx.x;
    g_pcnt[i] = 0.f;
    g_psum[i] = 0.f; g_psum[i + 256] = 0.f; g_psum[i + 512] = 0.f;
}

__global__ void k_pool_accum(const float* __restrict__ feat, const int* __restrict__ ids) {
    __shared__ float ss[96];
    __shared__ float sc[32];
    int tid = threadIdx.x;
    if (tid < 96) ss[tid] = 0.f;
    if (tid < 32) sc[tid] = 0.f;
    __syncthreads();
    int b = blockIdx.y;
    const int HW = 262144;
    const float* f0 = feat + (size_t)b * 3 * HW;
    const int* idp = ids + (size_t)b * HW;
    for (int i = blockIdx.x * blockDim.x + tid; i < HW; i += gridDim.x * blockDim.x) {
        int id = idp[i];
        atomicAdd(&ss[id * 3 + 0], f0[i]);
        atomicAdd(&ss[id * 3 + 1], f0[i + HW]);
        atomicAdd(&ss[id * 3 + 2], f0[i + 2 * HW]);
        atomicAdd(&sc[id], 1.f);
    }
    __syncthreads();
    if (tid < 96) atomicAdd(&g_psum[b * 96 + tid], ss[tid]);
    if (tid < 32) atomicAdd(&g_pcnt[b * 32 + tid], sc[tid]);
}

__global__ void k_pool_mean() {
    int i = threadIdx.x;
    float c = g_pcnt[i];
    c = c > 0.f ? c : 1.f;
    g_psum[i * 3 + 0] /= c; g_psum[i * 3 + 1] /= c; g_psum[i * 3 + 2] /= c;
}

__global__ void k_pool_scatter(const int* __restrict__ ids, float* __restrict__ out) {
    const int HW = 262144;
    int total = 8 * HW;
    for (int i = blockIdx.x * blockDim.x + threadIdx.x; i < total; i += gridDim.x * blockDim.x) {
        int b = i >> 18, p = i & (HW - 1);
        int id = ids[i];
        const float* m = &g_psum[(b * 32 + id) * 3];
        out[((size_t)(b * 3 + 0) << 18) + p] = m[0];
        out[((size_t)(b * 3 + 1) << 18) + p] = m[1];
        out[((size_t)(b * 3 + 2) << 18) + p] = m[2];
    }
}

// ---------------- host ----------------
static inline int ilog2i(int v) { int s = 0; while ((1 << s) < v) s++; return s; }

extern "C" void kernel_launch(void* const* d_in, const int* in_sizes, int n_in,
                              void* d_out, int out_size) {
    const float* x     = (const float*)d_in[0];
    const int*   imap  = (const int*)  d_in[1];
    const float* w_in  = (const float*)d_in[2];
    const float* b_in  = (const float*)d_in[3];
    const float* wd[4], *bd[4], *wu[4], *bu[4];
    for (int i = 0; i < 4; i++) {
        wd[i] = (const float*)d_in[4 + 2 * i];
        bd[i] = (const float*)d_in[5 + 2 * i];
        wu[i] = (const float*)d_in[12 + 2 * i];
        bu[i] = (const float*)d_in[13 + 2 * i];
    }
    const float* w_out = (const float*)d_in[20];
    const float* b_out = (const float*)d_in[21];

    static const size_t OFF[10] = {
        0u, 33817088u, 50857472u, 59510272u, 63970816u, 66338304u,
        70798848u, 79451648u, 96492032u, 130309120u
    };

    float* act;
    cudaGetSymbolAddress((void**)&act, g_act);
    float* outp = (float*)d_out;

    dim3 blk(16, 8);

    // input conv -> L0 (raw); stats + halo-fill prepare it for fused-norm consumption
    k_conv_in<<<dim3(32, 16, 8), blk>>>(x, w_in, b_in, act + OFF[0]);
    k_stats<<<8 * 16, 256>>>(act + OFF[0], 512, 9);
    k_halo<<<8 * 16, 256>>>(act + OFF[0], 512);

    int C = 16, H = 512;
    // down path: L_i -> L_{i+1} (norm+relu applied on load inside k_down)
    for (int i = 0; i < 4; i++) {
        int Cout = 2 * C, Hout = H / 2;
        dim3 g(Hout / 16, Hout / 32, 8 * (Cout / 8));
        k_down<<<g, blk>>>(act + OFF[i], wd[i], bd[i], act + OFF[i + 1], C, Cout, H);
        k_stats<<<8 * Cout, 256>>>(act + OFF[i + 1], Hout, ilog2i(Hout));
        k_halo<<<8 * Cout, 256>>>(act + OFF[i + 1], Hout);
        C = Cout; H = Hout;
    }

    // up path: L_{4+i} -> L_{5+i}
    for (int i = 0; i < 4; i++) {
        int Cout = C / 2, Hout = 2 * H;
        dim3 g(Hout / 32, Hout / 32, 8 * (Cout / 8));
        k_up<<<g, blk>>>(act + OFF[4 + i], wu[i], bu[i], act + OFF[5 + i], C, Cout, H);
        k_stats<<<8 * Cout, 256>>>(act + OFF[5 + i], Hout, ilog2i(Hout));
        if (i < 3)   // L8 is consumed by reflect-pad conv_out (interior only): no halo needed
            k_halo<<<8 * Cout, 256>>>(act + OFF[5 + i], Hout);
        C = Cout; H = Hout;
    }

    // output conv + tanh (norm+relu fused on load): L8 -> L9 (unpadded)
    k_conv_out<<<dim3(32, 8, 8), blk>>>(act + OFF[8], w_out, b_out, act + OFF[9]);

    // instance-mean pooling -> d_out
    k_pool_zero<<<1, 256>>>();
    k_pool_accum<<<dim3(64, 8), 256>>>(act + OFF[9], imap);
    k_pool_mean<<<1, 256>>>();
    k_pool_scatter<<<8192, 256>>>(imap, outp);
}

// round 12
// speedup vs baseline: 1.3378x; 1.0970x over previous
#include <cuda_runtime.h>
#include <math.h>

// ---------------- scratch arena (no allocation allowed) ----------------
__device__ float g_act[136600576];
__device__ float g_mean[2048];
__device__ float g_rstd[2048];
__device__ float g_psum[8 * 32 * 3];
__device__ float g_pcnt[8 * 32];

// ---------------- 7x7 reflect conv, 3 -> 16, 512x512, writes padded (raw) ----------------
// block(16,16): out tile 16x32, thread = 2 rows x 16 cout
__global__ __launch_bounds__(256) void k_conv_in(const float* __restrict__ x,
                                                 const float* __restrict__ w,
                                                 const float* __restrict__ bias,
                                                 float* __restrict__ out) {
    __shared__ __align__(16) float ws[2352];   // [ci3][k49][co16]
    __shared__ float tile[3 * 38 * 24];        // stride 24 (2*24 % 32 == 16)
    const int tx = threadIdx.x, ty = threadIdx.y;
    const int tid = ty * 16 + tx;
    const int ox0 = blockIdx.x * 16, oy0 = blockIdx.y * 32, b = blockIdx.z;

    for (int i = tid; i < 2352; i += 256) {
        int co = i & 15, rem = i >> 4, ci = rem / 49, k = rem % 49;
        ws[i] = w[co * 147 + ci * 49 + k];
    }
    for (int i = tid; i < 2508; i += 256) {
        int ci = i / 836, rem = i - ci * 836, r = rem / 22, c = rem % 22;
        int gy = oy0 + r - 3; gy = gy < 0 ? -gy : (gy > 511 ? 1022 - gy : gy);
        int gx = ox0 + c - 3; gx = gx < 0 ? -gx : (gx > 511 ? 1022 - gx : gx);
        tile[ci * 912 + r * 24 + c] = x[((size_t)(b * 3 + ci) << 18) + (gy << 9) + gx];
    }
    __syncthreads();

    float acc[2][16];
#pragma unroll
    for (int co = 0; co < 16; co++) {
        float bv = bias[co];
        acc[0][co] = bv; acc[1][co] = bv;
    }

#pragma unroll 1
    for (int ci = 0; ci < 3; ci++) {
#pragma unroll 1
        for (int ky = 0; ky < 7; ky++) {
            const float* rp = tile + ci * 912 + (2 * ty + ky) * 24 + tx;
            const float* wp = ws + (ci * 49 + ky * 7) * 16;
#pragma unroll
            for (int kx = 0; kx < 7; kx++) {
                float x0 = rp[kx], x1 = rp[kx + 24];
                float wreg[16];
                *(float4*)(wreg)      = *(const float4*)(wp + kx * 16);
                *(float4*)(wreg + 4)  = *(const float4*)(wp + kx * 16 + 4);
                *(float4*)(wreg + 8)  = *(const float4*)(wp + kx * 16 + 8);
                *(float4*)(wreg + 12) = *(const float4*)(wp + kx * 16 + 12);
#pragma unroll
                for (int co = 0; co < 16; co++) {
                    float wv = wreg[co];
                    acc[0][co] += x0 * wv; acc[1][co] += x1 * wv;
                }
            }
        }
    }
    int oy = oy0 + 2 * ty, ox = ox0 + tx;
#pragma unroll
    for (int co = 0; co < 16; co++) {
        float* op = out + (size_t)(b * 16 + co) * 264196 + (oy + 1) * 514 + ox + 1;
        op[0] = acc[0][co]; op[514] = acc[1][co];
    }
}

// ---------------- 7x7 reflect conv 16 -> 3 + tanh; norm+relu fused; 2-ch chunks ----------------
__global__ __launch_bounds__(128) void k_conv_out(const float* __restrict__ in,
                                                  const float* __restrict__ w,
                                                  const float* __restrict__ bias,
                                                  float* __restrict__ out) {
    __shared__ __align__(16) float ws[3136];   // [ci16][k49][co4pad]
    __shared__ float tile[2 * 70 * 26];
    const int tx = threadIdx.x, ty = threadIdx.y;
    const int tid = ty * 16 + tx;
    const int ox0 = blockIdx.x * 16, oy0 = blockIdx.y * 64, b = blockIdx.z;

    for (int i = tid; i < 3136; i += 128) {
        int co = i & 3, rem = i >> 2, ci = rem / 49, k = rem % 49;
        ws[i] = (co < 3) ? w[co * 784 + ci * 49 + k] : 0.f;
    }

    float acc[8][3];
#pragma unroll
    for (int co = 0; co < 3; co++) {
        float bv = bias[co];
#pragma unroll
        for (int r = 0; r < 8; r++) acc[r][co] = bv;
    }

#pragma unroll 1
    for (int ci0 = 0; ci0 < 16; ci0 += 2) {
        __syncthreads();
        for (int i = tid; i < 3080; i += 128) {
            int lci = i / 1540, rem = i - lci * 1540, r = rem / 22, c = rem % 22;
            int gy = oy0 + r - 3; gy = gy < 0 ? -gy : (gy > 511 ? 1022 - gy : gy);
            int gx = ox0 + c - 3; gx = gx < 0 ? -gx : (gx > 511 ? 1022 - gx : gx);
            int bc = b * 16 + ci0 + lci;
            float v = in[(size_t)bc * 264196 + (gy + 1) * 514 + gx + 1];
            tile[lci * 1820 + r * 26 + c] = fmaxf(0.f, (v - g_mean[bc]) * g_rstd[bc]);
        }
        __syncthreads();
#pragma unroll 1
        for (int lci = 0; lci < 2; lci++) {
            int ci = ci0 + lci;
#pragma unroll 1
            for (int ky = 0; ky < 7; ky++) {
                const float* rp = tile + lci * 1820 + (8 * ty + ky) * 26 + tx;
                const float* wp = ws + (ci * 49 + ky * 7) * 4;
#pragma unroll
                for (int kx = 0; kx < 7; kx++) {
                    float4 wv = *(const float4*)(wp + kx * 4);
#pragma unroll
                    for (int r = 0; r < 8; r++) {
                        float xv = rp[kx + r * 26];
                        acc[r][0] += xv * wv.x; acc[r][1] += xv * wv.y; acc[r][2] += xv * wv.z;
                    }
                }
            }
        }
    }
    int ox = ox0 + tx;
#pragma unroll
    for (int r = 0; r < 8; r++) {
        int oy = oy0 + 8 * ty + r;
#pragma unroll
        for (int co = 0; co < 3; co++)
            out[((size_t)(b * 3 + co) << 18) + (oy << 9) + ox] = tanhf(acc[r][co]);
    }
}

// ---------------- 3x3 stride-2 conv; norm+relu fused; block(16,16), 2 rows/thread ----------------
__global__ __launch_bounds__(256) void k_down(const float* __restrict__ in,
                                              const float* __restrict__ w,
                                              const float* __restrict__ bias,
                                              float* __restrict__ out,
                                              int Cin, int Cout, int Hin) {
    const int Wp = Hin + 2, PPin = Wp * Wp;
    const int Hout = Hin >> 1, Wop = Hout + 2, PPout = Wop * Wop;
    const int groups = Cout >> 3;
    const int b = blockIdx.z / groups, cog = (blockIdx.z % groups) * 8;
    const int ox0 = blockIdx.x * 16, oy0 = blockIdx.y * 32;
    __shared__ float tile[4 * 65 * 36];            // E cols 0..16, O at +18; stride 36
    __shared__ __align__(16) float ws[4 * 9 * 8];  // [lci][k][co]
    const int tx = threadIdx.x, ty = threadIdx.y;
    const int tid = ty * 16 + tx;
    const int ybase = 2 * oy0, xbase = 2 * ox0;

    float acc[2][8];
#pragma unroll
    for (int co = 0; co < 8; co++) {
        float bv = bias[cog + co];
        acc[0][co] = bv; acc[1][co] = bv;
    }

    for (int ci0 = 0; ci0 < Cin; ci0 += 4) {
        __syncthreads();
        for (int i = tid; i < 288; i += 256) {
            int co = i & 7, rem = i >> 3, lci = rem / 9, k = rem % 9;
            ws[i] = w[((size_t)(cog + co) * Cin + ci0 + lci) * 9 + k];
        }
        const int bcb = b * Cin + ci0;
#pragma unroll 1
        for (int lci = 0; lci < 4; lci++) {
            float m = g_mean[bcb + lci], rs = g_rstd[bcb + lci];
            const float* ip = in + (size_t)(bcb + lci) * PPin + (size_t)ybase * Wp + xbase;
            float* tp = tile + lci * 2340;
#pragma unroll 1
            for (int r = ty; r < 65; r += 16) {
                float2 v = *(const float2*)(ip + r * Wp + 2 * tx);
                tp[r * 36 + tx]      = fmaxf(0.f, (v.x - m) * rs);
                tp[r * 36 + 18 + tx] = fmaxf(0.f, (v.y - m) * rs);
            }
            if (tid < 65) {   // cols 32,33
                float2 v = *(const float2*)(ip + tid * Wp + 32);
                tp[tid * 36 + 16] = fmaxf(0.f, (v.x - m) * rs);
                tp[tid * 36 + 34] = fmaxf(0.f, (v.y - m) * rs);
            }
        }
        __syncthreads();
#pragma unroll 1
        for (int lci = 0; lci < 4; lci++) {
            const float* tl = tile + lci * 2340 + (4 * ty) * 36;
            const float* wl = ws + lci * 72;
#pragma unroll
            for (int ky = 0; ky < 3; ky++) {
#pragma unroll
                for (int kx = 0; kx < 3; kx++) {
                    int off = ky * 36 + (kx & 1) * 18 + tx + (kx >> 1);
                    float x0 = tl[off], x1 = tl[off + 72];
                    float wreg[8];
                    *(float4*)(wreg)     = *(const float4*)(wl + (ky * 3 + kx) * 8);
                    *(float4*)(wreg + 4) = *(const float4*)(wl + (ky * 3 + kx) * 8 + 4);
#pragma unroll
                    for (int co = 0; co < 8; co++) {
                        float wv = wreg[co];
                        acc[0][co] += x0 * wv; acc[1][co] += x1 * wv;
                    }
                }
            }
        }
    }
    int oy = oy0 + 2 * ty, ox = ox0 + tx;
#pragma unroll
    for (int co = 0; co < 8; co++) {
        float* op = out + (size_t)(b * Cout + cog + co) * PPout + (oy + 1) * Wop + ox + 1;
        op[0] = acc[0][co]; op[Wop] = acc[1][co];
    }
}

// ---------------- transposed 3x3 s2 p1 op1; norm+relu fused; block(32,8), 1 quad/thread ----------------
// out tile 64x16; thread quad at out(2ty,2tx) needs input (ty..ty+1, tx..tx+1).
__global__ __launch_bounds__(256) void k_up(const float* __restrict__ in,
                                            const float* __restrict__ w,
                                            const float* __restrict__ bias,
                                            float* __restrict__ out,
                                            int Cin, int Cout, int Hin) {
    const int Wp = Hin + 2, PPin = Wp * Wp;
    const int Hout = Hin * 2, Wop = Hout + 2, PPout = Wop * Wop;
    const int groups = Cout >> 3;
    const int b = blockIdx.z / groups, cog = (blockIdx.z % groups) * 8;
    const int ox0 = blockIdx.x * 64, oy0 = blockIdx.y * 16;
    const int iy0 = oy0 >> 1, ix0 = ox0 >> 1;
    __shared__ float tile[4 * 9 * 33];             // 9 rows x 33 cols per lci
    __shared__ __align__(16) float ws[4 * 8 * 12]; // [lci][co][12pad]
    const int tx = threadIdx.x, ty = threadIdx.y;
    const int tid = ty * 32 + tx;

    float acc[4][8];
#pragma unroll
    for (int co = 0; co < 8; co++) {
        float bv = bias[cog + co];
#pragma unroll
        for (int p = 0; p < 4; p++) acc[p][co] = bv;
    }

    for (int ci0 = 0; ci0 < Cin; ci0 += 4) {
        __syncthreads();
        for (int i = tid; i < 288; i += 256) {
            int lci = i / 72, rem = i - lci * 72, co = rem / 9, k = rem % 9;
            ws[lci * 96 + co * 12 + k] = w[((size_t)(ci0 + lci) * Cout + cog + co) * 9 + k];
        }
        const int bcb = b * Cin + ci0;
        for (int i = tid; i < 1188; i += 256) {
            int lci = i / 297, rem = i - lci * 297, r = rem / 33, c = rem - r * 33;
            int bc = bcb + lci;
            float v = in[(size_t)bc * PPin + (size_t)(iy0 + r + 1) * Wp + ix0 + c + 1];
            tile[lci * 297 + r * 33 + c] = fmaxf(0.f, (v - g_mean[bc]) * g_rstd[bc]);
        }
        __syncthreads();
#pragma unroll 1
        for (int lci = 0; lci < 4; lci++) {
            const float* tp = tile + lci * 297 + ty * 33 + tx;
            float v00 = tp[0],  v01 = tp[1];
            float v10 = tp[33], v11 = tp[34];
            const float* wl = ws + lci * 96;
#pragma unroll
            for (int co = 0; co < 8; co++) {
                float4 wa = *(const float4*)(wl + co * 12);     // w0 w1 w2 w3
                float4 wb = *(const float4*)(wl + co * 12 + 4); // w4 w5 w6 w7
                float w8 = wl[co * 12 + 8];
                acc[0][co] += v00 * wb.x;                                   // (2r,2c)
                acc[1][co] += v01 * wa.w + v00 * wb.y;                      // (2r,2c+1)
                acc[2][co] += v10 * wa.y + v00 * wb.w;                      // (2r+1,2c)
                acc[3][co] += v11 * wa.x + v10 * wa.z + v01 * wb.z + v00 * w8;
            }
        }
    }
#pragma unroll
    for (int p = 0; p < 4; p++) {
        int py = p >> 1, px = p & 1;
        int oy = oy0 + 2 * ty + py, ox = ox0 + 2 * tx + px;
#pragma unroll
        for (int co = 0; co < 8; co++)
            out[(size_t)(b * Cout + cog + co) * PPout + (oy + 1) * Wop + ox + 1] = acc[p][co];
    }
}

// ---------------- instance norm stats; 4 independent double accumulators ----------------
__global__ void k_stats(const float* __restrict__ base, int W, int logW) {
    int bc = blockIdx.x;
    const float* p = base + (size_t)bc * (W + 2) * (W + 2);
    int HW = W << logW;   // always a multiple of 1024 here
    double s1a = 0.0, s1b = 0.0, s1c = 0.0, s1d = 0.0;
    double s2a = 0.0, s2b = 0.0, s2c = 0.0, s2d = 0.0;
    for (int i = threadIdx.x; i < HW; i += 1024) {
        int r0 = i >> logW, c0 = i & (W - 1);
        float v0 = p[(r0 + 1) * (W + 2) + c0 + 1];
        int j = i + 256, r1 = j >> logW, c1 = j & (W - 1);
        float v1 = p[(r1 + 1) * (W + 2) + c1 + 1];
        int k = i + 512, r2 = k >> logW, c2 = k & (W - 1);
        float v2 = p[(r2 + 1) * (W + 2) + c2 + 1];
        int l = i + 768, r3 = l >> logW, c3 = l & (W - 1);
        float v3 = p[(r3 + 1) * (W + 2) + c3 + 1];
        s1a += v0; s2a += (double)v0 * v0;
        s1b += v1; s2b += (double)v1 * v1;
        s1c += v2; s2c += (double)v2 * v2;
        s1d += v3; s2d += (double)v3 * v3;
    }
    __shared__ double sh1[256], sh2[256];
    sh1[threadIdx.x] = (s1a + s1b) + (s1c + s1d);
    sh2[threadIdx.x] = (s2a + s2b) + (s2c + s2d);
    __syncthreads();
    for (int s = 128; s > 0; s >>= 1) {
        if (threadIdx.x < s) { sh1[threadIdx.x] += sh1[threadIdx.x + s]; sh2[threadIdx.x] += sh2[threadIdx.x + s]; }
        __syncthreads();
    }
    if (threadIdx.x == 0) {
        double m = sh1[0] / HW;
        double var = sh2[0] / HW - m * m;
        if (var < 0.0) var = 0.0;
        g_mean[bc] = (float)m;
        g_rstd[bc] = rsqrtf((float)var + 1e-5f);
    }
}

// Fill halo with mean[bc]: normalizes to exactly 0 (then relu -> 0).
__global__ void k_halo(float* __restrict__ base, int W) {
    int bc = blockIdx.x;
    float m = g_mean[bc];
    int Wp = W + 2;
    float* p = base + (size_t)bc * Wp * Wp;
    for (int i = threadIdx.x; i < Wp; i += 256) {
        p[i] = m;
        p[(size_t)(Wp - 1) * Wp + i] = m;
        p[(size_t)i * Wp] = m;
        p[(size_t)i * Wp + Wp - 1] = m;
    }
}

// ---------------- per-instance mean pooling ----------------
__global__ void k_pool_zero() {
    int i = threadIdx.x;
    g_pcnt[i] = 0.f;
    g_psum[i] = 0.f; g_psum[i + 256] = 0.f; g_psum[i + 512] = 0.f;
}

__global__ void k_pool_accum(const float* __restrict__ feat, const int* __restrict__ ids) {
    __shared__ float ss[96];
    __shared__ float sc[32];
    int tid = threadIdx.x;
    if (tid < 96) ss[tid] = 0.f;
    if (tid < 32) sc[tid] = 0.f;
    __syncthreads();
    int b = blockIdx.y;
    const int HW = 262144;
    const float* f0 = feat + (size_t)b * 3 * HW;
    const int* idp = ids + (size_t)b * HW;
    for (int i = blockIdx.x * blockDim.x + tid; i < HW; i += gridDim.x * blockDim.x) {
        int id = idp[i];
        atomicAdd(&ss[id * 3 + 0], f0[i]);
        atomicAdd(&ss[id * 3 + 1], f0[i + HW]);
        atomicAdd(&ss[id * 3 + 2], f0[i + 2 * HW]);
        atomicAdd(&sc[id], 1.f);
    }
    __syncthreads();
    if (tid < 96) atomicAdd(&g_psum[b * 96 + tid], ss[tid]);
    if (tid < 32) atomicAdd(&g_pcnt[b * 32 + tid], sc[tid]);
}

__global__ void k_pool_mean() {
    int i = threadIdx.x;
    float c = g_pcnt[i];
    c = c > 0.f ? c : 1.f;
    g_psum[i * 3 + 0] /= c; g_psum[i * 3 + 1] /= c; g_psum[i * 3 + 2] /= c;
}

__global__ void k_pool_scatter(const int* __restrict__ ids, float* __restrict__ out) {
    const int HW = 262144;
    int total = 8 * HW;
    for (int i = blockIdx.x * blockDim.x + threadIdx.x; i < total; i += gridDim.x * blockDim.x) {
        int b = i >> 18, p = i & (HW - 1);
        int id = ids[i];
        const float* m = &g_psum[(b * 32 + id) * 3];
        out[((size_t)(b * 3 + 0) << 18) + p] = m[0];
        out[((size_t)(b * 3 + 1) << 18) + p] = m[1];
        out[((size_t)(b * 3 + 2) << 18) + p] = m[2];
    }
}

// ---------------- host ----------------
static inline int ilog2i(int v) { int s = 0; while ((1 << s) < v) s++; return s; }

extern "C" void kernel_launch(void* const* d_in, const int* in_sizes, int n_in,
                              void* d_out, int out_size) {
    const float* x     = (const float*)d_in[0];
    const int*   imap  = (const int*)  d_in[1];
    const float* w_in  = (const float*)d_in[2];
    const float* b_in  = (const float*)d_in[3];
    const float* wd[4], *bd[4], *wu[4], *bu[4];
    for (int i = 0; i < 4; i++) {
        wd[i] = (const float*)d_in[4 + 2 * i];
        bd[i] = (const float*)d_in[5 + 2 * i];
        wu[i] = (const float*)d_in[12 + 2 * i];
        bu[i] = (const float*)d_in[13 + 2 * i];
    }
    const float* w_out = (const float*)d_in[20];
    const float* b_out = (const float*)d_in[21];

    static const size_t OFF[10] = {
        0u, 33817088u, 50857472u, 59510272u, 63970816u, 66338304u,
        70798848u, 79451648u, 96492032u, 130309120u
    };

    float* act;
    cudaGetSymbolAddress((void**)&act, g_act);
    float* outp = (float*)d_out;

    // input conv -> L0 (raw); stats + halo prepare for fused-norm consumers
    k_conv_in<<<dim3(32, 16, 8), dim3(16, 16)>>>(x, w_in, b_in, act + OFF[0]);
    k_stats<<<8 * 16, 256>>>(act + OFF[0], 512, 9);
    k_halo<<<8 * 16, 256>>>(act + OFF[0], 512);

    int C = 16, H = 512;
    // down path
    for (int i = 0; i < 4; i++) {
        int Cout = 2 * C, Hout = H / 2;
        dim3 g(Hout / 16, Hout / 32, 8 * (Cout / 8));
        k_down<<<g, dim3(16, 16)>>>(act + OFF[i], wd[i], bd[i], act + OFF[i + 1], C, Cout, H);
        k_stats<<<8 * Cout, 256>>>(act + OFF[i + 1], Hout, ilog2i(Hout));
        k_halo<<<8 * Cout, 256>>>(act + OFF[i + 1], Hout);
        C = Cout; H = Hout;
    }

    // up path
    for (int i = 0; i < 4; i++) {
        int Cout = C / 2, Hout = 2 * H;
        dim3 g(Hout / 64, Hout / 16, 8 * (Cout / 8));
        k_up<<<g, dim3(32, 8)>>>(act + OFF[4 + i], wu[i], bu[i], act + OFF[5 + i], C, Cout, H);
        k_stats<<<8 * Cout, 256>>>(act + OFF[5 + i], Hout, ilog2i(Hout));
        if (i < 3)   // L8 is consumed interior-only by reflect conv_out
            k_halo<<<8 * Cout, 256>>>(act + OFF[5 + i], Hout);
        C = Cout; H = Hout;
    }

    // output conv + tanh (norm+relu fused): L8 -> L9 (unpadded)
    k_conv_out<<<dim3(32, 8, 8), dim3(16, 8)>>>(act + OFF[8], w_out, b_out, act + OFF[9]);

    // instance-mean pooling -> d_out
    k_pool_zero<<<1, 256>>>();
    k_pool_accum<<<dim3(64, 8), 256>>>(act + OFF[9], imap);
    k_pool_mean<<<1, 256>>>();
    k_pool_scatter<<<8192, 256>>>(imap, outp);
}

// round 14
// speedup vs baseline: 1.7660x; 1.3201x over previous
#include <cuda_runtime.h>
#include <math.h>

// ---------------- scratch arena (no allocation allowed) ----------------
__device__ float g_act[136600576];
__device__ float g_mean[2048];
__device__ float g_rstd[2048];
__device__ double g_s1[6144];   // per-layer stat accumulators (finalize zeroes after read)
__device__ double g_s2[6144];
__device__ float g_psum[8 * 32 * 3];
__device__ float g_pcnt[8 * 32];

// ---------------- 7x7 reflect conv, 3 -> 16, 512x512, writes padded (raw) + stats ----------------
// block(16,16): out tile 16x32, thread = 2 rows x 16 cout
__global__ __launch_bounds__(256) void k_conv_in(const float* __restrict__ x,
                                                 const float* __restrict__ w,
                                                 const float* __restrict__ bias,
                                                 float* __restrict__ out,
                                                 double* __restrict__ s1,
                                                 double* __restrict__ s2) {
    __shared__ __align__(16) float ws[2352];   // [ci3][k49][co16]
    __shared__ float tile[3 * 38 * 24];        // stride 24 (2*24 % 32 == 16)
    __shared__ float sh_s[128], sh_q[128];
    const int tx = threadIdx.x, ty = threadIdx.y;
    const int tid = ty * 16 + tx;
    const int ox0 = blockIdx.x * 16, oy0 = blockIdx.y * 32, b = blockIdx.z;

    for (int i = tid; i < 2352; i += 256) {
        int co = i & 15, rem = i >> 4, ci = rem / 49, k = rem % 49;
        ws[i] = w[co * 147 + ci * 49 + k];
    }
    for (int i = tid; i < 2508; i += 256) {
        int ci = i / 836, rem = i - ci * 836, r = rem / 22, c = rem % 22;
        int gy = oy0 + r - 3; gy = gy < 0 ? -gy : (gy > 511 ? 1022 - gy : gy);
        int gx = ox0 + c - 3; gx = gx < 0 ? -gx : (gx > 511 ? 1022 - gx : gx);
        tile[ci * 912 + r * 24 + c] = x[((size_t)(b * 3 + ci) << 18) + (gy << 9) + gx];
    }
    __syncthreads();

    float acc[2][16];
#pragma unroll
    for (int co = 0; co < 16; co++) {
        float bv = bias[co];
        acc[0][co] = bv; acc[1][co] = bv;
    }

#pragma unroll 1
    for (int ci = 0; ci < 3; ci++) {
#pragma unroll 1
        for (int ky = 0; ky < 7; ky++) {
            const float* rp = tile + ci * 912 + (2 * ty + ky) * 24 + tx;
            const float* wp = ws + (ci * 49 + ky * 7) * 16;
#pragma unroll
            for (int kx = 0; kx < 7; kx++) {
                float x0 = rp[kx], x1 = rp[kx + 24];
                float wreg[16];
                *(float4*)(wreg)      = *(const float4*)(wp + kx * 16);
                *(float4*)(wreg + 4)  = *(const float4*)(wp + kx * 16 + 4);
                *(float4*)(wreg + 8)  = *(const float4*)(wp + kx * 16 + 8);
                *(float4*)(wreg + 12) = *(const float4*)(wp + kx * 16 + 12);
#pragma unroll
                for (int co = 0; co < 16; co++) {
                    float wv = wreg[co];
                    acc[0][co] += x0 * wv; acc[1][co] += x1 * wv;
                }
            }
        }
    }
    int oy = oy0 + 2 * ty, ox = ox0 + tx;
#pragma unroll
    for (int co = 0; co < 16; co++) {
        float* op = out + (size_t)(b * 16 + co) * 264196 + (oy + 1) * 514 + ox + 1;
        op[0] = acc[0][co]; op[514] = acc[1][co];
    }

    // fused stats partials
    int lane = tid & 31, wid = tid >> 5;
#pragma unroll
    for (int co = 0; co < 16; co++) {
        float sv = acc[0][co] + acc[1][co];
        float qv = acc[0][co] * acc[0][co] + acc[1][co] * acc[1][co];
#pragma unroll
        for (int o = 16; o > 0; o >>= 1) {
            sv += __shfl_down_sync(0xffffffffu, sv, o);
            qv += __shfl_down_sync(0xffffffffu, qv, o);
        }
        if (lane == 0) { sh_s[co * 8 + wid] = sv; sh_q[co * 8 + wid] = qv; }
    }
    __syncthreads();
    if (tid < 16) {
        float ts = 0.f, tq = 0.f;
#pragma unroll
        for (int wd = 0; wd < 8; wd++) { ts += sh_s[tid * 8 + wd]; tq += sh_q[tid * 8 + wd]; }
        atomicAdd(&s1[b * 16 + tid], (double)ts);
        atomicAdd(&s2[b * 16 + tid], (double)tq);
    }
}

// ---------------- 7x7 reflect conv 16 -> 3 + tanh; norm+relu fused; block(16,16) ----------------
__global__ __launch_bounds__(256) void k_conv_out(const float* __restrict__ in,
                                                  const float* __restrict__ w,
                                                  const float* __restrict__ bias,
                                                  float* __restrict__ out) {
    __shared__ __align__(16) float ws[3136];   // [ci16][k49][co4pad]
    __shared__ float tile[2 * 70 * 28];        // stride 28 (4*28 % 32 == 16)
    const int tx = threadIdx.x, ty = threadIdx.y;
    const int tid = ty * 16 + tx;
    const int ox0 = blockIdx.x * 16, oy0 = blockIdx.y * 64, b = blockIdx.z;

    for (int i = tid; i < 3136; i += 256) {
        int co = i & 3, rem = i >> 2, ci = rem / 49, k = rem % 49;
        ws[i] = (co < 3) ? w[co * 784 + ci * 49 + k] : 0.f;
    }

    float acc[4][3];
#pragma unroll
    for (int co = 0; co < 3; co++) {
        float bv = bias[co];
#pragma unroll
        for (int r = 0; r < 4; r++) acc[r][co] = bv;
    }

#pragma unroll 1
    for (int ci0 = 0; ci0 < 16; ci0 += 2) {
        __syncthreads();
        for (int i = tid; i < 3080; i += 256) {
            int lci = i / 1540, rem = i - lci * 1540, r = rem / 22, c = rem % 22;
            int gy = oy0 + r - 3; gy = gy < 0 ? -gy : (gy > 511 ? 1022 - gy : gy);
            int gx = ox0 + c - 3; gx = gx < 0 ? -gx : (gx > 511 ? 1022 - gx : gx);
            int bc = b * 16 + ci0 + lci;
            float v = in[(size_t)bc * 264196 + (gy + 1) * 514 + gx + 1];
            tile[lci * 1960 + r * 28 + c] = fmaxf(0.f, (v - g_mean[bc]) * g_rstd[bc]);
        }
        __syncthreads();
#pragma unroll 1
        for (int lci = 0; lci < 2; lci++) {
            int ci = ci0 + lci;
#pragma unroll 1
            for (int ky = 0; ky < 7; ky++) {
                const float* rp = tile + lci * 1960 + (4 * ty + ky) * 28 + tx;
                const float* wp = ws + (ci * 49 + ky * 7) * 4;
#pragma unroll
                for (int kx = 0; kx < 7; kx++) {
                    float4 wv = *(const float4*)(wp + kx * 4);
#pragma unroll
                    for (int r = 0; r < 4; r++) {
                        float xv = rp[kx + r * 28];
                        acc[r][0] += xv * wv.x; acc[r][1] += xv * wv.y; acc[r][2] += xv * wv.z;
                    }
                }
            }
        }
    }
    int ox = ox0 + tx;
#pragma unroll
    for (int r = 0; r < 4; r++) {
        int oy = oy0 + 4 * ty + r;
#pragma unroll
        for (int co = 0; co < 3; co++)
            out[((size_t)(b * 3 + co) << 18) + (oy << 9) + ox] = tanhf(acc[r][co]);
    }
}

// ---------------- 3x3 stride-2 conv; norm+relu fused; block(16,16), 2 rows/thread + stats ----------------
__global__ __launch_bounds__(256) void k_down(const float* __restrict__ in,
                                              const float* __restrict__ w,
                                              const float* __restrict__ bias,
                                              float* __restrict__ out,
                                              int Cin, int Cout, int Hin,
                                              double* __restrict__ s1,
                                              double* __restrict__ s2) {
    const int Wp = Hin + 2, PPin = Wp * Wp;
    const int Hout = Hin >> 1, Wop = Hout + 2, PPout = Wop * Wop;
    const int groups = Cout >> 3;
    const int b = blockIdx.z / groups, cog = (blockIdx.z % groups) * 8;
    const int ox0 = blockIdx.x * 16, oy0 = blockIdx.y * 32;
    __shared__ float tile[4 * 65 * 36];            // E cols 0..16, O at +18; stride 36
    __shared__ __align__(16) float ws[4 * 9 * 8];  // [lci][k][co]
    __shared__ float sh_s[64], sh_q[64];
    const int tx = threadIdx.x, ty = threadIdx.y;
    const int tid = ty * 16 + tx;
    const int ybase = 2 * oy0, xbase = 2 * ox0;

    float acc[2][8];
#pragma unroll
    for (int co = 0; co < 8; co++) {
        float bv = bias[cog + co];
        acc[0][co] = bv; acc[1][co] = bv;
    }

    for (int ci0 = 0; ci0 < Cin; ci0 += 4) {
        __syncthreads();
        for (int i = tid; i < 288; i += 256) {
            int co = i & 7, rem = i >> 3, lci = rem / 9, k = rem % 9;
            ws[i] = w[((size_t)(cog + co) * Cin + ci0 + lci) * 9 + k];
        }
        const int bcb = b * Cin + ci0;
#pragma unroll 1
        for (int lci = 0; lci < 4; lci++) {
            float m = g_mean[bcb + lci], rs = g_rstd[bcb + lci];
            const float* ip = in + (size_t)(bcb + lci) * PPin + (size_t)ybase * Wp + xbase;
            float* tp = tile + lci * 2340;
#pragma unroll 1
            for (int r = ty; r < 65; r += 16) {
                float2 v = *(const float2*)(ip + r * Wp + 2 * tx);
                tp[r * 36 + tx]      = fmaxf(0.f, (v.x - m) * rs);
                tp[r * 36 + 18 + tx] = fmaxf(0.f, (v.y - m) * rs);
            }
            if (tid < 65) {   // cols 32,33
                float2 v = *(const float2*)(ip + tid * Wp + 32);
                tp[tid * 36 + 16] = fmaxf(0.f, (v.x - m) * rs);
                tp[tid * 36 + 34] = fmaxf(0.f, (v.y - m) * rs);
            }
        }
        __syncthreads();
#pragma unroll 1
        for (int lci = 0; lci < 4; lci++) {
            const float* tl = tile + lci * 2340 + (4 * ty) * 36;
            const float* wl = ws + lci * 72;
#pragma unroll
            for (int ky = 0; ky < 3; ky++) {
#pragma unroll
                for (int kx = 0; kx < 3; kx++) {
                    int off = ky * 36 + (kx & 1) * 18 + tx + (kx >> 1);
                    float x0 = tl[off], x1 = tl[off + 72];
                    float wreg[8];
                    *(float4*)(wreg)     = *(const float4*)(wl + (ky * 3 + kx) * 8);
                    *(float4*)(wreg + 4) = *(const float4*)(wl + (ky * 3 + kx) * 8 + 4);
#pragma unroll
                    for (int co = 0; co < 8; co++) {
                        float wv = wreg[co];
                        acc[0][co] += x0 * wv; acc[1][co] += x1 * wv;
                    }
                }
            }
        }
    }
    int oy = oy0 + 2 * ty, ox = ox0 + tx;
#pragma unroll
    for (int co = 0; co < 8; co++) {
        float* op = out + (size_t)(b * Cout + cog + co) * PPout + (oy + 1) * Wop + ox + 1;
        op[0] = acc[0][co]; op[Wop] = acc[1][co];
    }

    // fused stats partials
    int lane = tid & 31, wid = tid >> 5;
#pragma unroll
    for (int co = 0; co < 8; co++) {
        float sv = acc[0][co] + acc[1][co];
        float qv = acc[0][co] * acc[0][co] + acc[1][co] * acc[1][co];
#pragma unroll
        for (int o = 16; o > 0; o >>= 1) {
            sv += __shfl_down_sync(0xffffffffu, sv, o);
            qv += __shfl_down_sync(0xffffffffu, qv, o);
        }
        if (lane == 0) { sh_s[co * 8 + wid] = sv; sh_q[co * 8 + wid] = qv; }
    }
    __syncthreads();
    if (tid < 8) {
        float ts = 0.f, tq = 0.f;
#pragma unroll
        for (int wd = 0; wd < 8; wd++) { ts += sh_s[tid * 8 + wd]; tq += sh_q[tid * 8 + wd]; }
        atomicAdd(&s1[b * Cout + cog + tid], (double)ts);
        atomicAdd(&s2[b * Cout + cog + tid], (double)tq);
    }
}

// ---------------- transposed 3x3 s2 p1 op1; norm+relu fused; block(32,8), 1 quad/thread + stats ----------------
__global__ __launch_bounds__(256) void k_up(const float* __restrict__ in,
                                            const float* __restrict__ w,
                                            const float* __restrict__ bias,
                                            float* __restrict__ out,
                                            int Cin, int Cout, int Hin,
                                            double* __restrict__ s1,
                                            double* __restrict__ s2) {
    const int Wp = Hin + 2, PPin = Wp * Wp;
    const int Hout = Hin * 2, Wop = Hout + 2, PPout = Wop * Wop;
    const int groups = Cout >> 3;
    const int b = blockIdx.z / groups, cog = (blockIdx.z % groups) * 8;
    const int ox0 = blockIdx.x * 64, oy0 = blockIdx.y * 16;
    const int iy0 = oy0 >> 1, ix0 = ox0 >> 1;
    __shared__ float tile[4 * 9 * 33];             // 9 rows x 33 cols per lci
    __shared__ __align__(16) float ws[4 * 8 * 12]; // [lci][co][12pad]
    __shared__ float sh_s[64], sh_q[64];
    const int tx = threadIdx.x, ty = threadIdx.y;
    const int tid = ty * 32 + tx;

    float acc[4][8];
#pragma unroll
    for (int co = 0; co < 8; co++) {
        float bv = bias[cog + co];
#pragma unroll
        for (int p = 0; p < 4; p++) acc[p][co] = bv;
    }

    for (int ci0 = 0; ci0 < Cin; ci0 += 4) {
        __syncthreads();
        for (int i = tid; i < 288; i += 256) {
            int lci = i / 72, rem = i - lci * 72, co = rem / 9, k = rem % 9;
            ws[lci * 96 + co * 12 + k] = w[((size_t)(ci0 + lci) * Cout + cog + co) * 9 + k];
        }
        const int bcb = b * Cin + ci0;
        for (int i = tid; i < 1188; i += 256) {
            int lci = i / 297, rem = i - lci * 297, r = rem / 33, c = rem - r * 33;
            int bc = bcb + lci;
            float v = in[(size_t)bc * PPin + (size_t)(iy0 + r + 1) * Wp + ix0 + c + 1];
            tile[lci * 297 + r * 33 + c] = fmaxf(0.f, (v - g_mean[bc]) * g_rstd[bc]);
        }
        __syncthreads();
#pragma unroll 1
        for (int lci = 0; lci < 4; lci++) {
            const float* tp = tile + lci * 297 + ty * 33 + tx;
            float v00 = tp[0],  v01 = tp[1];
            float v10 = tp[33], v11 = tp[34];
            const float* wl = ws + lci * 96;
#pragma unroll
            for (int co = 0; co < 8; co++) {
                float4 wa = *(const float4*)(wl + co * 12);     // w0 w1 w2 w3
                float4 wb = *(const float4*)(wl + co * 12 + 4); // w4 w5 w6 w7
                float w8 = wl[co * 12 + 8];
                acc[0][co] += v00 * wb.x;                                   // (2r,2c)
                acc[1][co] += v01 * wa.w + v00 * wb.y;                      // (2r,2c+1)
                acc[2][co] += v10 * wa.y + v00 * wb.w;                      // (2r+1,2c)
                acc[3][co] += v11 * wa.x + v10 * wa.z + v01 * wb.z + v00 * w8;
            }
        }
    }
#pragma unroll
    for (int p = 0; p < 4; p++) {
        int py = p >> 1, px = p & 1;
        int oy = oy0 + 2 * ty + py, ox = ox0 + 2 * tx + px;
#pragma unroll
        for (int co = 0; co < 8; co++)
            out[(size_t)(b * Cout + cog + co) * PPout + (oy + 1) * Wop + ox + 1] = acc[p][co];
    }

    // fused stats partials
    int lane = tid & 31, wid = tid >> 5;
#pragma unroll
    for (int co = 0; co < 8; co++) {
        float sv = (acc[0][co] + acc[1][co]) + (acc[2][co] + acc[3][co]);
        float qv = (acc[0][co] * acc[0][co] + acc[1][co] * acc[1][co]) +
                   (acc[2][co] * acc[2][co] + acc[3][co] * acc[3][co]);
#pragma unroll
        for (int o = 16; o > 0; o >>= 1) {
            sv += __shfl_down_sync(0xffffffffu, sv, o);
            qv += __shfl_down_sync(0xffffffffu, qv, o);
        }
        if (lane == 0) { sh_s[co * 8 + wid] = sv; sh_q[co * 8 + wid] = qv; }
    }
    __syncthreads();
    if (tid < 8) {
        float ts = 0.f, tq = 0.f;
#pragma unroll
        for (int wd = 0; wd < 8; wd++) { ts += sh_s[tid * 8 + wd]; tq += sh_q[tid * 8 + wd]; }
        atomicAdd(&s1[b * Cout + cog + tid], (double)ts);
        atomicAdd(&s2[b * Cout + cog + tid], (double)tq);
    }
}

// ---------------- finalize: mean/rstd from accumulators, fill halo, zero accumulators ----------------
__global__ void k_finalize(double* __restrict__ s1, double* __restrict__ s2,
                           float* __restrict__ base, int W, int HW, int do_halo) {
    int bc = blockIdx.x;
    __shared__ float smv;
    if (threadIdx.x == 0) {
        double m = s1[bc] / HW;
        double var = s2[bc] / HW - m * m;
        if (var < 0.0) var = 0.0;
        g_mean[bc] = (float)m;
        g_rstd[bc] = rsqrtf((float)var + 1e-5f);
        s1[bc] = 0.0; s2[bc] = 0.0;   // ready for next graph replay
        smv = (float)m;
    }
    __syncthreads();
    if (do_halo) {
        float m = smv;
        int Wp = W + 2;
        float* p = base + (size_t)bc * Wp * Wp;
        for (int i = threadIdx.x; i < Wp; i += 256) {
            p[i] = m;
            p[(size_t)(Wp - 1) * Wp + i] = m;
            p[(size_t)i * Wp] = m;
            p[(size_t)i * Wp + Wp - 1] = m;
        }
    }
}

// ---------------- per-instance mean pooling ----------------
__global__ void k_pool_zero() {
    int i = threadIdx.x;
    g_pcnt[i] = 0.f;
    g_psum[i] = 0.f; g_psum[i + 256] = 0.f; g_psum[i + 512] = 0.f;
}

__global__ void k_pool_accum(const float* __restrict__ feat, const int* __restrict__ ids) {
    __shared__ float ss[96];
    __shared__ float sc[32];
    int tid = threadIdx.x;
    if (tid < 96) ss[tid] = 0.f;
    if (tid < 32) sc[tid] = 0.f;
    __syncthreads();
    int b = blockIdx.y;
    const int HW = 262144;
    const float* f0 = feat + (size_t)b * 3 * HW;
    const int* idp = ids + (size_t)b * HW;
    for (int i = blockIdx.x * blockDim.x + tid; i < HW; i += gridDim.x * blockDim.x) {
        int id = idp[i];
        atomicAdd(&ss[id * 3 + 0], f0[i]);
        atomicAdd(&ss[id * 3 + 1], f0[i + HW]);
        atomicAdd(&ss[id * 3 + 2], f0[i + 2 * HW]);
        atomicAdd(&sc[id], 1.f);
    }
    __syncthreads();
    if (tid < 96) atomicAdd(&g_psum[b * 96 + tid], ss[tid]);
    if (tid < 32) atomicAdd(&g_pcnt[b * 32 + tid], sc[tid]);
}

__global__ void k_pool_mean() {
    int i = threadIdx.x;
    float c = g_pcnt[i];
    c = c > 0.f ? c : 1.f;
    g_psum[i * 3 + 0] /= c; g_psum[i * 3 + 1] /= c; g_psum[i * 3 + 2] /= c;
}

__global__ void k_pool_scatter(const int* __restrict__ ids, float* __restrict__ out) {
    const int HW = 262144;
    int total = 8 * HW;
    for (int i = blockIdx.x * blockDim.x + threadIdx.x; i < total; i += gridDim.x * blockDim.x) {
        int b = i >> 18, p = i & (HW - 1);
        int id = ids[i];
        const float* m = &g_psum[(b * 32 + id) * 3];
        out[((size_t)(b * 3 + 0) << 18) + p] = m[0];
        out[((size_t)(b * 3 + 1) << 18) + p] = m[1];
        out[((size_t)(b * 3 + 2) << 18) + p] = m[2];
    }
}

// ---------------- host ----------------
extern "C" void kernel_launch(void* const* d_in, const int* in_sizes, int n_in,
                              void* d_out, int out_size) {
    const float* x     = (const float*)d_in[0];
    const int*   imap  = (const int*)  d_in[1];
    const float* w_in  = (const float*)d_in[2];
    const float* b_in  = (const float*)d_in[3];
    const float* wd[4], *bd[4], *wu[4], *bu[4];
    for (int i = 0; i < 4; i++) {
        wd[i] = (const float*)d_in[4 + 2 * i];
        bd[i] = (const float*)d_in[5 + 2 * i];
        wu[i] = (const float*)d_in[12 + 2 * i];
        bu[i] = (const float*)d_in[13 + 2 * i];
    }
    const float* w_out = (const float*)d_in[20];
    const float* b_out = (const float*)d_in[21];

    static const size_t OFF[10] = {
        0u, 33817088u, 50857472u, 59510272u, 63970816u, 66338304u,
        70798848u, 79451648u, 96492032u, 130309120u
    };
    // per-layer stat-accumulator offsets: 8 * cumsum(channels 16,32,64,128,256,128,64,32,16)
    static const int SOFF[9] = {0, 128, 384, 896, 1920, 3968, 4992, 5504, 5760};

    float* act;
    double *s1, *s2;
    cudaGetSymbolAddress((void**)&act, g_act);
    cudaGetSymbolAddress((void**)&s1, g_s1);
    cudaGetSymbolAddress((void**)&s2, g_s2);
    float* outp = (float*)d_out;

    // input conv -> L0 (raw) + fused stats; finalize computes mean/rstd + halo
    k_conv_in<<<dim3(32, 16, 8), dim3(16, 16)>>>(x, w_in, b_in, act + OFF[0],
                                                 s1 + SOFF[0], s2 + SOFF[0]);
    k_finalize<<<8 * 16, 256>>>(s1 + SOFF[0], s2 + SOFF[0], act + OFF[0], 512, 262144, 1);

    int C = 16, H = 512;
    // down path
    for (int i = 0; i < 4; i++) {
        int Cout = 2 * C, Hout = H / 2;
        dim3 g(Hout / 16, Hout / 32, 8 * (Cout / 8));
        k_down<<<g, dim3(16, 16)>>>(act + OFF[i], wd[i], bd[i], act + OFF[i + 1], C, Cout, H,
                                    s1 + SOFF[i + 1], s2 + SOFF[i + 1]);
        k_finalize<<<8 * Cout, 256>>>(s1 + SOFF[i + 1], s2 + SOFF[i + 1],
                                      act + OFF[i + 1], Hout, Hout * Hout, 1);
        C = Cout; H = Hout;
    }

    // up path
    for (int i = 0; i < 4; i++) {
        int Cout = C / 2, Hout = 2 * H;
        dim3 g(Hout / 64, Hout / 16, 8 * (Cout / 8));
        k_up<<<g, dim3(32, 8)>>>(act + OFF[4 + i], wu[i], bu[i], act + OFF[5 + i], C, Cout, H,
                                 s1 + SOFF[5 + i], s2 + SOFF[5 + i]);
        k_finalize<<<8 * Cout, 256>>>(s1 + SOFF[5 + i], s2 + SOFF[5 + i],
                                      act + OFF[5 + i], Hout, Hout * Hout, i < 3 ? 1 : 0);
        C = Cout; H = Hout;
    }

    // output conv + tanh (norm+relu fused): L8 -> L9 (unpadded)
    k_conv_out<<<dim3(32, 8, 8), dim3(16, 16)>>>(act + OFF[8], w_out, b_out, act + OFF[9]);

    // instance-mean pooling -> d_out
    k_pool_zero<<<1, 256>>>();
    k_pool_accum<<<dim3(64, 8), 256>>>(act + OFF[9], imap);
    k_pool_mean<<<1, 256>>>();
    k_pool_scatter<<<8192, 256>>>(imap, outp);
}